// round 1
// baseline (speedup 1.0000x reference)
#include <cuda_runtime.h>

#define NN   4096
#define INF  256
#define HH   128
#define NW   128      // mask words per row (4096 bits / 32)
#define RR   8        // rows per attention block

// ---------------- scratch (device globals: no allocations allowed) ----------
__device__ float    g_W1h[NN * HH];
__device__ float    g_W2hT[HH * NN];
__device__ float    g_s1[NN];
__device__ float    g_s2[NN];
__device__ unsigned g_M1[NN * NW];
__device__ unsigned g_M2[NN * NW];
__device__ unsigned g_M3[NN * NW];
__device__ float    g_hk[NN * HH];

// ---------------- K1: W1h = X@W1^T, W2h^T = (X@W2^T)^T ----------------------
// 32 X-rows per block, 256 threads: t<128 -> W1 column t, t>=128 -> W2 column.
__global__ void prep_kernel(const float* __restrict__ X,
                            const float* __restrict__ W1,
                            const float* __restrict__ W2) {
    __shared__ float xs[32][INF];           // 32 KB
    const int t    = threadIdx.x;
    const int row0 = blockIdx.x * 32;

    const float4* Xv  = reinterpret_cast<const float4*>(X + (size_t)row0 * INF);
    float4*       xsv = reinterpret_cast<float4*>(&xs[0][0]);
    for (int k = t; k < 32 * INF / 4; k += 256) xsv[k] = Xv[k];
    __syncthreads();

    const float* W = (t < HH) ? (W1 + (size_t)t * INF)
                              : (W2 + (size_t)(t - HH) * INF);
    float acc[32];
#pragma unroll
    for (int rr = 0; rr < 32; rr++) acc[rr] = 0.f;

    for (int c = 0; c < INF; c += 4) {
        float4 w4 = *reinterpret_cast<const float4*>(W + c);
#pragma unroll
        for (int rr = 0; rr < 32; rr++) {
            float4 x4 = *reinterpret_cast<const float4*>(&xs[rr][c]);
            acc[rr] += x4.x * w4.x + x4.y * w4.y + x4.z * w4.z + x4.w * w4.w;
        }
    }
#pragma unroll
    for (int rr = 0; rr < 32; rr++) {
        const int row = row0 + rr;
        if (t < HH) g_W1h[(size_t)row * HH + t] = acc[rr];
        else        g_W2hT[(size_t)(t - HH) * NN + row] = acc[rr];
    }
}

// ---------------- K2: s1 = W1h @ r[:H], s2 = W1h @ r[H:] --------------------
__global__ void s12_kernel(const float* __restrict__ r) {
    const int i = blockIdx.x, t = threadIdx.x;     // 128 threads
    const float w  = g_W1h[(size_t)i * HH + t];
    float v1 = w * r[t];
    float v2 = w * r[HH + t];
#pragma unroll
    for (int o = 16; o; o >>= 1) {
        v1 += __shfl_xor_sync(0xFFFFFFFFu, v1, o);
        v2 += __shfl_xor_sync(0xFFFFFFFFu, v2, o);
    }
    __shared__ float sh1[4], sh2[4];
    if ((t & 31) == 0) { sh1[t >> 5] = v1; sh2[t >> 5] = v2; }
    __syncthreads();
    if (t == 0) g_s1[i] = sh1[0] + sh1[1] + sh1[2] + sh1[3];
    if (t == 1) g_s2[i] = sh2[0] + sh2[1] + sh2[2] + sh2[3];
}

// ---------------- K3: bitmask of A --------------------------------------------
__global__ void maskbuild_kernel(const float* __restrict__ A) {
    const int gid = blockIdx.x * 256 + threadIdx.x;   // N*N threads
    const float a = A[gid];
    const unsigned b = __ballot_sync(0xFFFFFFFFu, a != 0.0f);
    if ((threadIdx.x & 31) == 0) g_M1[gid >> 5] = b;
}

// ---------------- K4: boolean mat-power (zero pattern of A^k) -----------------
// mode 0: M2[i] = OR over k in M1[i] of M1[k];  mode 1: M3[i] = OR of M2[k].
__global__ void boolmm_kernel(int mode) {
    const unsigned* Min  = (mode == 0) ? g_M1 : g_M2;
    unsigned*       Mout = (mode == 0) ? g_M2 : g_M3;
    const int i = blockIdx.x, t = threadIdx.x;        // 128 threads
    __shared__ unsigned sh[NW];
    sh[t] = g_M1[(size_t)i * NW + t];
    __syncthreads();
    unsigned acc = 0;
    for (int w = 0; w < NW; w++) {
        unsigned bits = sh[w];                        // uniform across threads
        while (bits) {
            const int b = __ffs(bits) - 1;
            bits &= bits - 1;
            acc |= Min[(size_t)(w * 32 + b) * NW + t];
        }
    }
    Mout[(size_t)i * NW + t] = acc;
}

// ---------------- K5: attention 1: h_k = softmax(mask(e)) @ W1h ---------------
// Block = 8 rows, 128 threads. e[i,j] = lrelu(s1[i]+s2[j]); shift-by-40 softmax
// (no max pass; masked entries are exactly 0, matching exp(-1000-m) underflow).
__global__ void attn1_kernel(int hop) {
    const unsigned* M = (hop == 0) ? g_M1 : (hop == 1) ? g_M2 : g_M3;
    const int t  = threadIdx.x;
    const int i0 = blockIdx.x * RR;

    __shared__ unsigned msk[RR][NW];
    __shared__ __align__(16) float P[RR][128];
    __shared__ float Zsh[RR];

    for (int k = t; k < RR * NW; k += 128) (&msk[0][0])[k] = M[(size_t)i0 * NW + k];
    if (t < RR) Zsh[t] = 0.f;

    float s1v[RR], acc[RR], zloc[RR];
#pragma unroll
    for (int r = 0; r < RR; r++) {
        s1v[r] = g_s1[i0 + r];
        acc[r] = 0.f; zloc[r] = 0.f;
    }
    __syncthreads();

    for (int j0 = 0; j0 < NN; j0 += 128) {
        // ---- scores+exp for 128 j's (thread t <-> column j0+t)
        const int j   = j0 + t;
        const float s2j = g_s2[j];
        const int wi = j >> 5, bi = j & 31;
#pragma unroll
        for (int r = 0; r < RR; r++) {
            const float e  = s1v[r] + s2j;
            const float lr = fmaxf(e, 0.2f * e);      // leaky_relu
            float p = 0.f;
            if ((msk[r][wi] >> bi) & 1u) p = __expf(lr - 40.0f);
            P[r][t] = p;
            zloc[r] += p;
        }
        __syncthreads();
        // ---- V accumulation (thread t <-> channel t)
        const float* V = g_W1h + (size_t)j0 * HH;
#pragma unroll 2
        for (int jc = 0; jc < 128; jc += 4) {
            const float v0 = V[(jc + 0) * HH + t];
            const float v1 = V[(jc + 1) * HH + t];
            const float v2 = V[(jc + 2) * HH + t];
            const float v3 = V[(jc + 3) * HH + t];
#pragma unroll
            for (int r = 0; r < RR; r++) {
                const float4 p4 = *reinterpret_cast<const float4*>(&P[r][jc]);
                acc[r] += p4.x * v0;
                acc[r] += p4.y * v1;
                acc[r] += p4.z * v2;
                acc[r] += p4.w * v3;
            }
        }
        __syncthreads();
    }
#pragma unroll
    for (int r = 0; r < RR; r++) {
        float z = zloc[r];
#pragma unroll
        for (int o = 16; o; o >>= 1) z += __shfl_xor_sync(0xFFFFFFFFu, z, o);
        if ((t & 31) == 0) atomicAdd(&Zsh[r], z);
    }
    __syncthreads();
#pragma unroll
    for (int r = 0; r < RR; r++)
        g_hk[(size_t)(i0 + r) * HH + t] = acc[r] / Zsh[r];
}

// ---------------- K6: attention 2: out += softmax(mask(h@W2h^T)) @ h ----------
__global__ void attn2_kernel(int hop, float* __restrict__ Oacc, int accumulate) {
    const unsigned* M = (hop == 0) ? g_M1 : (hop == 1) ? g_M2 : g_M3;
    const int t  = threadIdx.x;
    const int i0 = blockIdx.x * RR;

    __shared__ unsigned msk[RR][NW];
    __shared__ __align__(16) float P[RR][128];
    __shared__ __align__(16) float hsh[RR][HH];
    __shared__ float Zsh[RR];

    for (int k = t; k < RR * NW; k += 128) (&msk[0][0])[k] = M[(size_t)i0 * NW + k];
    for (int k = t; k < RR * HH; k += 128) (&hsh[0][0])[k] = g_hk[(size_t)i0 * HH + k];
    if (t < RR) Zsh[t] = 0.f;

    float acc[RR], zloc[RR];
#pragma unroll
    for (int r = 0; r < RR; r++) { acc[r] = 0.f; zloc[r] = 0.f; }
    __syncthreads();

    for (int j0 = 0; j0 < NN; j0 += 128) {
        const int j = j0 + t;
        // ---- QK^T dots: thread t owns column j, all 8 rows
        float d[RR];
#pragma unroll
        for (int r = 0; r < RR; r++) d[r] = 0.f;
#pragma unroll 2
        for (int c = 0; c < HH; c += 4) {
            const float w0 = g_W2hT[(size_t)(c + 0) * NN + j];
            const float w1 = g_W2hT[(size_t)(c + 1) * NN + j];
            const float w2 = g_W2hT[(size_t)(c + 2) * NN + j];
            const float w3 = g_W2hT[(size_t)(c + 3) * NN + j];
#pragma unroll
            for (int r = 0; r < RR; r++) {
                const float4 h4 = *reinterpret_cast<const float4*>(&hsh[r][c]);
                d[r] += h4.x * w0;
                d[r] += h4.y * w1;
                d[r] += h4.z * w2;
                d[r] += h4.w * w3;
            }
        }
        const int wi = j >> 5, bi = j & 31;
#pragma unroll
        for (int r = 0; r < RR; r++) {
            float p = 0.f;
            if ((msk[r][wi] >> bi) & 1u) p = __expf(d[r]);
            P[r][t] = p;
            zloc[r] += p;
        }
        __syncthreads();
        // ---- V accumulation (V = h_k rows)
        const float* V = g_hk + (size_t)j0 * HH;
#pragma unroll 2
        for (int jc = 0; jc < 128; jc += 4) {
            const float v0 = V[(jc + 0) * HH + t];
            const float v1 = V[(jc + 1) * HH + t];
            const float v2 = V[(jc + 2) * HH + t];
            const float v3 = V[(jc + 3) * HH + t];
#pragma unroll
            for (int r = 0; r < RR; r++) {
                const float4 p4 = *reinterpret_cast<const float4*>(&P[r][jc]);
                acc[r] += p4.x * v0;
                acc[r] += p4.y * v1;
                acc[r] += p4.z * v2;
                acc[r] += p4.w * v3;
            }
        }
        __syncthreads();
    }
#pragma unroll
    for (int r = 0; r < RR; r++) {
        float z = zloc[r];
#pragma unroll
        for (int o = 16; o; o >>= 1) z += __shfl_xor_sync(0xFFFFFFFFu, z, o);
        if ((t & 31) == 0) atomicAdd(&Zsh[r], z);
    }
    __syncthreads();
#pragma unroll
    for (int r = 0; r < RR; r++) {
        const float o   = acc[r] / Zsh[r];
        const size_t ix = (size_t)(i0 + r) * HH + t;
        Oacc[ix] = accumulate ? (Oacc[ix] + o) : o;
    }
}

// ---------------- K7: U_out = U_l + O_l ---------------------------------------
__global__ void final_kernel(const float* __restrict__ U, float* __restrict__ out) {
    const int g = blockIdx.x * 256 + threadIdx.x;     // N*H threads
    out[g] = U[g] + out[NN * HH + g];
}

// ---------------- launch ------------------------------------------------------
extern "C" void kernel_launch(void* const* d_in, const int* in_sizes, int n_in,
                              void* d_out, int out_size) {
    const float* X  = (const float*)d_in[0];
    const float* A  = (const float*)d_in[1];
    const float* U  = (const float*)d_in[2];
    const float* W1 = (const float*)d_in[3];
    const float* W2 = (const float*)d_in[4];
    const float* r  = (const float*)d_in[5];
    float* out  = (float*)d_out;
    float* Oacc = out + (size_t)NN * HH;   // second half of output = O_l

    prep_kernel<<<NN / 32, 256>>>(X, W1, W2);
    s12_kernel<<<NN, 128>>>(r);
    maskbuild_kernel<<<NN * NN / 256, 256>>>(A);
    boolmm_kernel<<<NN, 128>>>(0);         // M2 = pattern(A^2)
    boolmm_kernel<<<NN, 128>>>(1);         // M3 = pattern(A^3)

    // hop 0
    attn1_kernel<<<NN / RR, 128>>>(0);
    attn2_kernel<<<NN / RR, 128>>>(0, Oacc, 0);   // overwrite (poisoned d_out)
    // hop 1
    attn1_kernel<<<NN / RR, 128>>>(1);
    attn2_kernel<<<NN / RR, 128>>>(1, Oacc, 1);
    // hop 2
    attn1_kernel<<<NN / RR, 128>>>(2);
    attn2_kernel<<<NN / RR, 128>>>(2, Oacc, 1);

    final_kernel<<<NN * HH / 256, 256>>>(U, out);
}

// round 2
// speedup vs baseline: 2.4395x; 2.4395x over previous
#include <cuda_runtime.h>

#define NN   4096
#define INF  256
#define HH   128
#define NW   128      // mask words per row (4096 bits / 32)
#define RR   8        // rows per dense attention block

// ---------------- scratch (device globals: no allocations allowed) ----------
__device__ float    g_W1h[NN * HH];     // row-major  [N][H]
__device__ float    g_W2h[NN * HH];     // row-major  [N][H]   (sparse path)
__device__ float    g_W2hT[HH * NN];    // transposed [H][N]   (dense path)
__device__ float    g_s1[NN];
__device__ float    g_s2[NN];
__device__ unsigned g_M1[NN * NW];
__device__ unsigned g_M2[NN * NW];
__device__ unsigned g_M3[NN * NW];
__device__ float    g_hk[NN * HH];

// ---------------- K1: W1h = X@W1^T, W2h(+T) = X@W2^T ------------------------
__global__ void prep_kernel(const float* __restrict__ X,
                            const float* __restrict__ W1,
                            const float* __restrict__ W2) {
    __shared__ float xs[32][INF];           // 32 KB
    const int t    = threadIdx.x;
    const int row0 = blockIdx.x * 32;

    const float4* Xv  = reinterpret_cast<const float4*>(X + (size_t)row0 * INF);
    float4*       xsv = reinterpret_cast<float4*>(&xs[0][0]);
    for (int k = t; k < 32 * INF / 4; k += 256) xsv[k] = Xv[k];
    __syncthreads();

    const float* W = (t < HH) ? (W1 + (size_t)t * INF)
                              : (W2 + (size_t)(t - HH) * INF);
    float acc[32];
#pragma unroll
    for (int rr = 0; rr < 32; rr++) acc[rr] = 0.f;

    for (int c = 0; c < INF; c += 4) {
        float4 w4 = *reinterpret_cast<const float4*>(W + c);
#pragma unroll
        for (int rr = 0; rr < 32; rr++) {
            float4 x4 = *reinterpret_cast<const float4*>(&xs[rr][c]);
            acc[rr] += x4.x * w4.x + x4.y * w4.y + x4.z * w4.z + x4.w * w4.w;
        }
    }
#pragma unroll
    for (int rr = 0; rr < 32; rr++) {
        const int row = row0 + rr;
        if (t < HH) {
            g_W1h[(size_t)row * HH + t] = acc[rr];
        } else {
            g_W2h[(size_t)row * HH + (t - HH)]   = acc[rr];
            g_W2hT[(size_t)(t - HH) * NN + row]  = acc[rr];
        }
    }
}

// ---------------- K2: s1 = W1h @ r[:H], s2 = W1h @ r[H:] --------------------
__global__ void s12_kernel(const float* __restrict__ r) {
    const int i = blockIdx.x, t = threadIdx.x;     // 128 threads
    const float w  = g_W1h[(size_t)i * HH + t];
    float v1 = w * r[t];
    float v2 = w * r[HH + t];
#pragma unroll
    for (int o = 16; o; o >>= 1) {
        v1 += __shfl_xor_sync(0xFFFFFFFFu, v1, o);
        v2 += __shfl_xor_sync(0xFFFFFFFFu, v2, o);
    }
    __shared__ float sh1[4], sh2[4];
    if ((t & 31) == 0) { sh1[t >> 5] = v1; sh2[t >> 5] = v2; }
    __syncthreads();
    if (t == 0) g_s1[i] = sh1[0] + sh1[1] + sh1[2] + sh1[3];
    if (t == 1) g_s2[i] = sh2[0] + sh2[1] + sh2[2] + sh2[3];
}

// ---------------- K3: bitmask of A --------------------------------------------
__global__ void maskbuild_kernel(const float* __restrict__ A) {
    const int gid = blockIdx.x * 256 + threadIdx.x;
    const float a = A[gid];
    const unsigned b = __ballot_sync(0xFFFFFFFFu, a != 0.0f);
    if ((threadIdx.x & 31) == 0) g_M1[gid >> 5] = b;
}

// ---------------- K4: boolean mat-power (zero pattern of A^k) -----------------
__global__ void boolmm_kernel(int mode) {
    const unsigned* Min  = (mode == 0) ? g_M1 : g_M2;
    unsigned*       Mout = (mode == 0) ? g_M2 : g_M3;
    const int i = blockIdx.x, t = threadIdx.x;        // 128 threads
    __shared__ unsigned sh[NW];
    sh[t] = g_M1[(size_t)i * NW + t];
    __syncthreads();
    unsigned acc = 0;
    for (int w = 0; w < NW; w++) {
        unsigned bits = sh[w];
        while (bits) {
            const int b = __ffs(bits) - 1;
            bits &= bits - 1;
            acc |= Min[(size_t)(w * 32 + b) * NW + t];
        }
    }
    Mout[(size_t)i * NW + t] = acc;
}

// ============ deterministic mask-row compaction helper (device inline) ========
// 128 threads. Returns n; fills idxs[] in ascending j order.
__device__ __forceinline__ int compact_row(const unsigned* __restrict__ M, int i,
                                           int* idxs, int* wsum, int& off_out) {
    const int t = threadIdx.x, l = t & 31, w = t >> 5;
    const unsigned word = M[(size_t)i * NW + t];
    int c = __popc(word);
    int sc = c;
#pragma unroll
    for (int o = 1; o < 32; o <<= 1) {
        int v = __shfl_up_sync(0xFFFFFFFFu, sc, o);
        if (l >= o) sc += v;
    }
    if (l == 31) wsum[w] = sc;
    __syncthreads();
    int base = 0;
#pragma unroll
    for (int q = 0; q < 4; q++) if (q < w) base += wsum[q];
    int off = base + sc - c;
    unsigned b = word;
    while (b) {
        const int bit = __ffs(b) - 1;
        b &= b - 1;
        idxs[off++] = t * 32 + bit;
    }
    off_out = base + sc - c;   // start offset for this thread (for p writes)
    __syncthreads();
    return wsum[0] + wsum[1] + wsum[2] + wsum[3];
}

// ---------------- K5s: SPARSE attention 1 (hops 0,1) --------------------------
// One block (128 thr) per row i. h[i] = sum_j p_j * W1h[j] / Z over masked j.
__global__ void sattn1_kernel(int hop) {
    const unsigned* M = (hop == 0) ? g_M1 : g_M2;
    const int i = blockIdx.x, t = threadIdx.x;
    __shared__ int   idxs[NN];
    __shared__ float plist[NN];
    __shared__ int   wsum[4];

    int myoff;
    const int n = compact_row(M, i, idxs, wsum, myoff);

    // compute p for the indices this thread emitted
    const float s1i = g_s1[i];
    {
        const unsigned word = M[(size_t)i * NW + t];
        unsigned b = word; int off = myoff;
        while (b) {
            const int bit = __ffs(b) - 1;
            b &= b - 1;
            const int j = t * 32 + bit;
            const float e  = s1i + g_s2[j];
            const float lr = fmaxf(e, 0.2f * e);
            plist[off++] = __expf(lr - 40.0f);
        }
    }
    __syncthreads();

    float a0 = 0.f, a1 = 0.f, a2 = 0.f, a3 = 0.f;
    float z0 = 0.f, z1 = 0.f, z2 = 0.f, z3 = 0.f;
    int k = 0;
    for (; k + 4 <= n; k += 4) {
        const float p0 = plist[k], p1 = plist[k+1], p2 = plist[k+2], p3 = plist[k+3];
        const int j0 = idxs[k], j1 = idxs[k+1], j2 = idxs[k+2], j3 = idxs[k+3];
        a0 = fmaf(p0, g_W1h[(size_t)j0 * HH + t], a0); z0 += p0;
        a1 = fmaf(p1, g_W1h[(size_t)j1 * HH + t], a1); z1 += p1;
        a2 = fmaf(p2, g_W1h[(size_t)j2 * HH + t], a2); z2 += p2;
        a3 = fmaf(p3, g_W1h[(size_t)j3 * HH + t], a3); z3 += p3;
    }
    for (; k < n; k++) {
        const float p = plist[k];
        a0 = fmaf(p, g_W1h[(size_t)idxs[k] * HH + t], a0); z0 += p;
    }
    const float acc = (a0 + a1) + (a2 + a3);
    const float z   = (z0 + z1) + (z2 + z3);
    g_hk[(size_t)i * HH + t] = acc / z;
}

// ---------------- K6s: SPARSE attention 2 (hops 0,1) --------------------------
__global__ void sattn2_kernel(int hop, float* __restrict__ Oacc, int accumulate) {
    const unsigned* M = (hop == 0) ? g_M1 : g_M2;
    const int i = blockIdx.x, t = threadIdx.x, l = t & 31, w = t >> 5;
    __shared__ int   idxs[NN];
    __shared__ float plist[NN];
    __shared__ int   wsum[4];

    // h_i channels for the warp-dot phase
    const float hv0 = g_hk[(size_t)i * HH + l];
    const float hv1 = g_hk[(size_t)i * HH + l + 32];
    const float hv2 = g_hk[(size_t)i * HH + l + 64];
    const float hv3 = g_hk[(size_t)i * HH + l + 96];

    int myoff;
    const int n = compact_row(M, i, idxs, wsum, myoff);

    // phase B: scores d_j = h_i . W2h[j], p = exp(d). Warp per j, 2-way unrolled.
    int k = w;
    for (; k + 4 < n; k += 8) {
        const int ja = idxs[k], jb = idxs[k + 4];
        const float* Wa = g_W2h + (size_t)ja * HH;
        const float* Wb = g_W2h + (size_t)jb * HH;
        float da = hv0 * Wa[l] + hv1 * Wa[l+32] + hv2 * Wa[l+64] + hv3 * Wa[l+96];
        float db = hv0 * Wb[l] + hv1 * Wb[l+32] + hv2 * Wb[l+64] + hv3 * Wb[l+96];
#pragma unroll
        for (int o = 16; o; o >>= 1) {
            da += __shfl_xor_sync(0xFFFFFFFFu, da, o);
            db += __shfl_xor_sync(0xFFFFFFFFu, db, o);
        }
        if (l == 0) { plist[k] = __expf(da); plist[k + 4] = __expf(db); }
    }
    for (; k < n; k += 4) {
        const int j = idxs[k];
        const float* W = g_W2h + (size_t)j * HH;
        float d = hv0 * W[l] + hv1 * W[l+32] + hv2 * W[l+64] + hv3 * W[l+96];
#pragma unroll
        for (int o = 16; o; o >>= 1) d += __shfl_xor_sync(0xFFFFFFFFu, d, o);
        if (l == 0) plist[k] = __expf(d);
    }
    __syncthreads();

    // phase C: PV gather over h rows
    float a0 = 0.f, a1 = 0.f, a2 = 0.f, a3 = 0.f;
    float z0 = 0.f, z1 = 0.f, z2 = 0.f, z3 = 0.f;
    k = 0;
    for (; k + 4 <= n; k += 4) {
        const float p0 = plist[k], p1 = plist[k+1], p2 = plist[k+2], p3 = plist[k+3];
        const int j0 = idxs[k], j1 = idxs[k+1], j2 = idxs[k+2], j3 = idxs[k+3];
        a0 = fmaf(p0, g_hk[(size_t)j0 * HH + t], a0); z0 += p0;
        a1 = fmaf(p1, g_hk[(size_t)j1 * HH + t], a1); z1 += p1;
        a2 = fmaf(p2, g_hk[(size_t)j2 * HH + t], a2); z2 += p2;
        a3 = fmaf(p3, g_hk[(size_t)j3 * HH + t], a3); z3 += p3;
    }
    for (; k < n; k++) {
        const float p = plist[k];
        a0 = fmaf(p, g_hk[(size_t)idxs[k] * HH + t], a0); z0 += p;
    }
    const float o = ((a0 + a1) + (a2 + a3)) / ((z0 + z1) + (z2 + z3));
    const size_t ix = (size_t)i * HH + t;
    Oacc[ix] = accumulate ? (Oacc[ix] + o) : o;
}

// ---------------- K5d: DENSE attention 1 (hop 2, M3) --------------------------
// 8 rows/block, 256 threads, 256-wide j chunks; PV split over two halves.
__global__ void dattn1_kernel() {
    const int t  = threadIdx.x;
    const int h  = t >> 7, tl = t & 127, jb = h << 7;
    const int i0 = blockIdx.x * RR;

    __shared__ unsigned msk[RR][NW];
    __shared__ __align__(16) float P[RR][256];
    __shared__ float Pacc[RR][HH];
    __shared__ float Zsh[RR];

    for (int k = t; k < RR * NW; k += 256) (&msk[0][0])[k] = g_M3[(size_t)i0 * NW + k];
    if (t < RR) Zsh[t] = 0.f;

    float s1v[RR], acc[RR], zl[RR];
#pragma unroll
    for (int r = 0; r < RR; r++) {
        s1v[r] = g_s1[i0 + r]; acc[r] = 0.f; zl[r] = 0.f;
    }
    __syncthreads();

    for (int j0 = 0; j0 < NN; j0 += 256) {
        const int j = j0 + t;
        const float s2j = g_s2[j];
        const int wi = j >> 5, bi = j & 31;
#pragma unroll
        for (int r = 0; r < RR; r++) {
            const float e  = s1v[r] + s2j;
            const float lr = fmaxf(e, 0.2f * e);
            float p = 0.f;
            if ((msk[r][wi] >> bi) & 1u) p = __expf(lr - 40.0f);
            P[r][t] = p;
            zl[r] += p;
        }
        __syncthreads();
        const float* V = g_W1h + (size_t)(j0 + jb) * HH;
#pragma unroll 2
        for (int jc = 0; jc < 128; jc += 4) {
            const float v0 = V[(jc + 0) * HH + tl];
            const float v1 = V[(jc + 1) * HH + tl];
            const float v2 = V[(jc + 2) * HH + tl];
            const float v3 = V[(jc + 3) * HH + tl];
#pragma unroll
            for (int r = 0; r < RR; r++) {
                const float4 p4 = *reinterpret_cast<const float4*>(&P[r][jb + jc]);
                acc[r] += p4.x * v0;
                acc[r] += p4.y * v1;
                acc[r] += p4.z * v2;
                acc[r] += p4.w * v3;
            }
        }
        __syncthreads();
    }
#pragma unroll
    for (int r = 0; r < RR; r++) {
        float z = zl[r];
#pragma unroll
        for (int o = 16; o; o >>= 1) z += __shfl_xor_sync(0xFFFFFFFFu, z, o);
        if ((t & 31) == 0) atomicAdd(&Zsh[r], z);
    }
    if (h == 1) {
#pragma unroll
        for (int r = 0; r < RR; r++) Pacc[r][tl] = acc[r];
    }
    __syncthreads();
    if (h == 0) {
#pragma unroll
        for (int r = 0; r < RR; r++)
            g_hk[(size_t)(i0 + r) * HH + tl] = (acc[r] + Pacc[r][tl]) / Zsh[r];
    }
}

// ---------------- K6d: DENSE attention 2 (hop 2, M3) --------------------------
__global__ void dattn2_kernel(float* __restrict__ Oacc) {
    const int t  = threadIdx.x;
    const int h  = t >> 7, tl = t & 127, jb = h << 7;
    const int i0 = blockIdx.x * RR;

    __shared__ unsigned msk[RR][NW];
    __shared__ __align__(16) float P[RR][256];
    __shared__ __align__(16) float hsh[RR][HH];
    __shared__ float Pacc[RR][HH];
    __shared__ float Zsh[RR];

    for (int k = t; k < RR * NW; k += 256) (&msk[0][0])[k] = g_M3[(size_t)i0 * NW + k];
    for (int k = t; k < RR * HH; k += 256) (&hsh[0][0])[k] = g_hk[(size_t)i0 * HH + k];
    if (t < RR) Zsh[t] = 0.f;

    float acc[RR], zl[RR];
#pragma unroll
    for (int r = 0; r < RR; r++) { acc[r] = 0.f; zl[r] = 0.f; }
    __syncthreads();

    for (int j0 = 0; j0 < NN; j0 += 256) {
        const int j = j0 + t;
        float d[RR];
#pragma unroll
        for (int r = 0; r < RR; r++) d[r] = 0.f;
#pragma unroll 2
        for (int c = 0; c < HH; c += 4) {
            const float w0 = g_W2hT[(size_t)(c + 0) * NN + j];
            const float w1 = g_W2hT[(size_t)(c + 1) * NN + j];
            const float w2 = g_W2hT[(size_t)(c + 2) * NN + j];
            const float w3 = g_W2hT[(size_t)(c + 3) * NN + j];
#pragma unroll
            for (int r = 0; r < RR; r++) {
                const float4 h4 = *reinterpret_cast<const float4*>(&hsh[r][c]);
                d[r] += h4.x * w0;
                d[r] += h4.y * w1;
                d[r] += h4.z * w2;
                d[r] += h4.w * w3;
            }
        }
        const int wi = j >> 5, bi = j & 31;
#pragma unroll
        for (int r = 0; r < RR; r++) {
            float p = 0.f;
            if ((msk[r][wi] >> bi) & 1u) p = __expf(d[r]);
            P[r][t] = p;
            zl[r] += p;
        }
        __syncthreads();
        const float* V = g_hk + (size_t)(j0 + jb) * HH;
#pragma unroll 2
        for (int jc = 0; jc < 128; jc += 4) {
            const float v0 = V[(jc + 0) * HH + tl];
            const float v1 = V[(jc + 1) * HH + tl];
            const float v2 = V[(jc + 2) * HH + tl];
            const float v3 = V[(jc + 3) * HH + tl];
#pragma unroll
            for (int r = 0; r < RR; r++) {
                const float4 p4 = *reinterpret_cast<const float4*>(&P[r][jb + jc]);
                acc[r] += p4.x * v0;
                acc[r] += p4.y * v1;
                acc[r] += p4.z * v2;
                acc[r] += p4.w * v3;
            }
        }
        __syncthreads();
    }
#pragma unroll
    for (int r = 0; r < RR; r++) {
        float z = zl[r];
#pragma unroll
        for (int o = 16; o; o >>= 1) z += __shfl_xor_sync(0xFFFFFFFFu, z, o);
        if ((t & 31) == 0) atomicAdd(&Zsh[r], z);
    }
    if (h == 1) {
#pragma unroll
        for (int r = 0; r < RR; r++) Pacc[r][tl] = acc[r];
    }
    __syncthreads();
    if (h == 0) {
#pragma unroll
        for (int r = 0; r < RR; r++) {
            const float o  = (acc[r] + Pacc[r][tl]) / Zsh[r];
            const size_t ix = (size_t)(i0 + r) * HH + tl;
            Oacc[ix] += o;
        }
    }
}

// ---------------- K7: U_out = U_l + O_l ---------------------------------------
__global__ void final_kernel(const float* __restrict__ U, float* __restrict__ out) {
    const int g = blockIdx.x * 256 + threadIdx.x;
    out[g] = U[g] + out[NN * HH + g];
}

// ---------------- launch ------------------------------------------------------
extern "C" void kernel_launch(void* const* d_in, const int* in_sizes, int n_in,
                              void* d_out, int out_size) {
    const float* X  = (const float*)d_in[0];
    const float* A  = (const float*)d_in[1];
    const float* U  = (const float*)d_in[2];
    const float* W1 = (const float*)d_in[3];
    const float* W2 = (const float*)d_in[4];
    const float* r  = (const float*)d_in[5];
    float* out  = (float*)d_out;
    float* Oacc = out + (size_t)NN * HH;   // second half of output = O_l

    prep_kernel<<<NN / 32, 256>>>(X, W1, W2);
    s12_kernel<<<NN, 128>>>(r);
    maskbuild_kernel<<<NN * NN / 256, 256>>>(A);
    boolmm_kernel<<<NN, 128>>>(0);         // M2 = pattern(A^2)
    boolmm_kernel<<<NN, 128>>>(1);         // M3 = pattern(A^3)

    // hop 0 (sparse, ~17 nnz/row)
    sattn1_kernel<<<NN, 128>>>(0);
    sattn2_kernel<<<NN, 128>>>(0, Oacc, 0);   // overwrite (d_out is poisoned)
    // hop 1 (sparse, ~280 nnz/row)
    sattn1_kernel<<<NN, 128>>>(1);
    sattn2_kernel<<<NN, 128>>>(1, Oacc, 1);
    // hop 2 (dense, ~70% nnz)
    dattn1_kernel<<<NN / RR, 256>>>();
    dattn2_kernel<<<NN / RR, 256>>>(Oacc);

    final_kernel<<<NN * HH / 256, 256>>>(U, out);
}

// round 4
// speedup vs baseline: 3.6977x; 1.5158x over previous
#include <cuda_runtime.h>

#define NN   4096
#define INF  256
#define HH   128
#define NW   128      // mask words per row (4096 bits / 32)
#define KSJ  2048     // j-range per K-split block (split = 2)

// ---------------- scratch (device globals: no allocations allowed) ----------
__device__ float    g_W1h[NN * HH];     // row-major  [N][H]
__device__ float    g_W2h[NN * HH];     // row-major  [N][H]
__device__ float    g_s1[NN];
__device__ float    g_s2[NN];
__device__ unsigned g_M1[NN * NW];
__device__ unsigned g_M2[NN * NW];
__device__ unsigned g_M3[NN * NW];
__device__ float    g_hk[NN * HH];
__device__ float    g_hp[2 * NN * HH];  // split-K partial accumulators
__device__ float    g_zp[2 * NN];       // split-K partial Z

// ---------------- tf32 helpers ----------------------------------------------
__device__ __forceinline__ float tfr(float f) {          // round fp32 -> tf32
    unsigned u;
    asm("cvt.rna.tf32.f32 %0, %1;" : "=r"(u) : "f"(f));
    return __uint_as_float(u);
}
__device__ __forceinline__ void mma_tf32(float* c, const unsigned* a, const unsigned* b) {
    asm("mma.sync.aligned.m16n8k8.row.col.f32.tf32.tf32.f32 "
        "{%0,%1,%2,%3},{%4,%5,%6,%7},{%8,%9},{%0,%1,%2,%3};"
        : "+f"(c[0]), "+f"(c[1]), "+f"(c[2]), "+f"(c[3])
        : "r"(a[0]), "r"(a[1]), "r"(a[2]), "r"(a[3]), "r"(b[0]), "r"(b[1]));
}

// ---------------- K1: W1h = X@W1^T, W2h = X@W2^T -----------------------------
__global__ void prep_kernel(const float* __restrict__ X,
                            const float* __restrict__ W1,
                            const float* __restrict__ W2) {
    __shared__ float xs[32][INF];
    const int t    = threadIdx.x;
    const int row0 = blockIdx.x * 32;

    const float4* Xv  = reinterpret_cast<const float4*>(X + (size_t)row0 * INF);
    float4*       xsv = reinterpret_cast<float4*>(&xs[0][0]);
    for (int k = t; k < 32 * INF / 4; k += 256) xsv[k] = Xv[k];
    __syncthreads();

    const float* W = (t < HH) ? (W1 + (size_t)t * INF)
                              : (W2 + (size_t)(t - HH) * INF);
    float acc[32];
#pragma unroll
    for (int rr = 0; rr < 32; rr++) acc[rr] = 0.f;

    for (int c = 0; c < INF; c += 4) {
        float4 w4 = *reinterpret_cast<const float4*>(W + c);
#pragma unroll
        for (int rr = 0; rr < 32; rr++) {
            float4 x4 = *reinterpret_cast<const float4*>(&xs[rr][c]);
            acc[rr] += x4.x * w4.x + x4.y * w4.y + x4.z * w4.z + x4.w * w4.w;
        }
    }
#pragma unroll
    for (int rr = 0; rr < 32; rr++) {
        const int row = row0 + rr;
        if (t < HH) g_W1h[(size_t)row * HH + t] = acc[rr];
        else        g_W2h[(size_t)row * HH + (t - HH)] = acc[rr];
    }
}

// ---------------- K2: s1 = W1h @ r[:H], s2 = W1h @ r[H:] --------------------
__global__ void s12_kernel(const float* __restrict__ r) {
    const int i = blockIdx.x, t = threadIdx.x;
    const float w  = g_W1h[(size_t)i * HH + t];
    float v1 = w * r[t];
    float v2 = w * r[HH + t];
#pragma unroll
    for (int o = 16; o; o >>= 1) {
        v1 += __shfl_xor_sync(0xFFFFFFFFu, v1, o);
        v2 += __shfl_xor_sync(0xFFFFFFFFu, v2, o);
    }
    __shared__ float sh1[4], sh2[4];
    if ((t & 31) == 0) { sh1[t >> 5] = v1; sh2[t >> 5] = v2; }
    __syncthreads();
    if (t == 0) g_s1[i] = sh1[0] + sh1[1] + sh1[2] + sh1[3];
    if (t == 1) g_s2[i] = sh2[0] + sh2[1] + sh2[2] + sh2[3];
}

// ---------------- K3: bitmask of A -------------------------------------------
__global__ void maskbuild_kernel(const float* __restrict__ A) {
    const int gid = blockIdx.x * 256 + threadIdx.x;
    const float a = A[gid];
    const unsigned b = __ballot_sync(0xFFFFFFFFu, a != 0.0f);
    if ((threadIdx.x & 31) == 0) g_M1[gid >> 5] = b;
}

// ---------------- K4: boolean mat-power --------------------------------------
__global__ void boolmm_kernel(int mode) {
    const unsigned* Min  = (mode == 0) ? g_M1 : g_M2;
    unsigned*       Mout = (mode == 0) ? g_M2 : g_M3;
    const int i = blockIdx.x, t = threadIdx.x;
    __shared__ unsigned sh[NW];
    sh[t] = g_M1[(size_t)i * NW + t];
    __syncthreads();
    unsigned acc = 0;
    for (int w = 0; w < NW; w++) {
        unsigned bits = sh[w];
        while (bits) {
            const int b = __ffs(bits) - 1;
            bits &= bits - 1;
            acc |= Min[(size_t)(w * 32 + b) * NW + t];
        }
    }
    Mout[(size_t)i * NW + t] = acc;
}

// ============ deterministic mask-row compaction (sparse hops) =================
__device__ __forceinline__ int compact_row(const unsigned* __restrict__ M, int i,
                                           int* idxs, int* wsum, int& off_out) {
    const int t = threadIdx.x, l = t & 31, w = t >> 5;
    const unsigned word = M[(size_t)i * NW + t];
    int c = __popc(word);
    int sc = c;
#pragma unroll
    for (int o = 1; o < 32; o <<= 1) {
        int v = __shfl_up_sync(0xFFFFFFFFu, sc, o);
        if (l >= o) sc += v;
    }
    if (l == 31) wsum[w] = sc;
    __syncthreads();
    int base = 0;
#pragma unroll
    for (int q = 0; q < 4; q++) if (q < w) base += wsum[q];
    int off = base + sc - c;
    unsigned b = word;
    while (b) {
        const int bit = __ffs(b) - 1;
        b &= b - 1;
        idxs[off++] = t * 32 + bit;
    }
    off_out = base + sc - c;
    __syncthreads();
    return wsum[0] + wsum[1] + wsum[2] + wsum[3];
}

// ---------------- K5s: SPARSE attention 1 (hops 0,1) -------------------------
__global__ void sattn1_kernel(int hop) {
    const unsigned* M = (hop == 0) ? g_M1 : g_M2;
    const int i = blockIdx.x, t = threadIdx.x;
    __shared__ int   idxs[NN];
    __shared__ float plist[NN];
    __shared__ int   wsum[4];

    int myoff;
    const int n = compact_row(M, i, idxs, wsum, myoff);

    const float s1i = g_s1[i];
    {
        const unsigned word = M[(size_t)i * NW + t];
        unsigned b = word; int off = myoff;
        while (b) {
            const int bit = __ffs(b) - 1;
            b &= b - 1;
            const int j = t * 32 + bit;
            const float e  = s1i + g_s2[j];
            const float lr = fmaxf(e, 0.2f * e);
            plist[off++] = __expf(lr - 40.0f);
        }
    }
    __syncthreads();

    float a0 = 0.f, a1 = 0.f, a2 = 0.f, a3 = 0.f;
    float z0 = 0.f, z1 = 0.f, z2 = 0.f, z3 = 0.f;
    int k = 0;
    for (; k + 4 <= n; k += 4) {
        const float p0 = plist[k], p1 = plist[k+1], p2 = plist[k+2], p3 = plist[k+3];
        const int j0 = idxs[k], j1 = idxs[k+1], j2 = idxs[k+2], j3 = idxs[k+3];
        a0 = fmaf(p0, g_W1h[(size_t)j0 * HH + t], a0); z0 += p0;
        a1 = fmaf(p1, g_W1h[(size_t)j1 * HH + t], a1); z1 += p1;
        a2 = fmaf(p2, g_W1h[(size_t)j2 * HH + t], a2); z2 += p2;
        a3 = fmaf(p3, g_W1h[(size_t)j3 * HH + t], a3); z3 += p3;
    }
    for (; k < n; k++) {
        const float p = plist[k];
        a0 = fmaf(p, g_W1h[(size_t)idxs[k] * HH + t], a0); z0 += p;
    }
    const float acc = (a0 + a1) + (a2 + a3);
    const float z   = (z0 + z1) + (z2 + z3);
    g_hk[(size_t)i * HH + t] = acc / z;
}

// ---------------- K6s: SPARSE attention 2 (hops 0,1) -------------------------
__global__ void sattn2_kernel(int hop, float* __restrict__ Oacc, int accumulate) {
    const unsigned* M = (hop == 0) ? g_M1 : g_M2;
    const int i = blockIdx.x, t = threadIdx.x, l = t & 31, w = t >> 5;
    __shared__ int   idxs[NN];
    __shared__ float plist[NN];
    __shared__ int   wsum[4];

    const float hv0 = g_hk[(size_t)i * HH + l];
    const float hv1 = g_hk[(size_t)i * HH + l + 32];
    const float hv2 = g_hk[(size_t)i * HH + l + 64];
    const float hv3 = g_hk[(size_t)i * HH + l + 96];

    int myoff;
    const int n = compact_row(M, i, idxs, wsum, myoff);

    int k = w;
    for (; k + 4 < n; k += 8) {
        const int ja = idxs[k], jb = idxs[k + 4];
        const float* Wa = g_W2h + (size_t)ja * HH;
        const float* Wb = g_W2h + (size_t)jb * HH;
        float da = hv0 * Wa[l] + hv1 * Wa[l+32] + hv2 * Wa[l+64] + hv3 * Wa[l+96];
        float db = hv0 * Wb[l] + hv1 * Wb[l+32] + hv2 * Wb[l+64] + hv3 * Wb[l+96];
#pragma unroll
        for (int o = 16; o; o >>= 1) {
            da += __shfl_xor_sync(0xFFFFFFFFu, da, o);
            db += __shfl_xor_sync(0xFFFFFFFFu, db, o);
        }
        if (l == 0) { plist[k] = __expf(da); plist[k + 4] = __expf(db); }
    }
    for (; k < n; k += 4) {
        const int j = idxs[k];
        const float* W = g_W2h + (size_t)j * HH;
        float d = hv0 * W[l] + hv1 * W[l+32] + hv2 * W[l+64] + hv3 * W[l+96];
#pragma unroll
        for (int o = 16; o; o >>= 1) d += __shfl_xor_sync(0xFFFFFFFFu, d, o);
        if (l == 0) plist[k] = __expf(d);
    }
    __syncthreads();

    float a0 = 0.f, a1 = 0.f, a2 = 0.f, a3 = 0.f;
    float z0 = 0.f, z1 = 0.f, z2 = 0.f, z3 = 0.f;
    k = 0;
    for (; k + 4 <= n; k += 4) {
        const float p0 = plist[k], p1 = plist[k+1], p2 = plist[k+2], p3 = plist[k+3];
        const int j0 = idxs[k], j1 = idxs[k+1], j2 = idxs[k+2], j3 = idxs[k+3];
        a0 = fmaf(p0, g_hk[(size_t)j0 * HH + t], a0); z0 += p0;
        a1 = fmaf(p1, g_hk[(size_t)j1 * HH + t], a1); z1 += p1;
        a2 = fmaf(p2, g_hk[(size_t)j2 * HH + t], a2); z2 += p2;
        a3 = fmaf(p3, g_hk[(size_t)j3 * HH + t], a3); z3 += p3;
    }
    for (; k < n; k++) {
        const float p = plist[k];
        a0 = fmaf(p, g_hk[(size_t)idxs[k] * HH + t], a0); z0 += p;
    }
    const float o = ((a0 + a1) + (a2 + a3)) / ((z0 + z1) + (z2 + z3));
    const size_t ix = (size_t)i * HH + t;
    Oacc[ix] = accumulate ? (Oacc[ix] + o) : o;
}

// ================= TENSOR-CORE dense hop-2 kernels ===========================
// Layout: 256 thr = 8 warps as (wm 0..1) x (wn 0..3). Block tile M=32 rows.
// grid = (N/32 M-tiles, 2 K-splits). mma.sync m16n8k8 tf32.

// ---- K5t: h partials = [masked softmax-numerator(e)] @ W1h ------------------
__global__ __launch_bounds__(256, 2) void dattn1_tc() {
    const int t = threadIdx.x, warp = t >> 5, lane = t & 31;
    const int gid = lane >> 2, tig = lane & 3;
    const int wm = warp >> 2, wn = warp & 3;
    const int i0 = blockIdx.x * 32;
    const int jlo = blockIdx.y * KSJ;
    const int r1 = wm * 16 + gid, r2 = r1 + 8;

    __shared__ float s2s[NN];          // 16 KB
    __shared__ float Vt[32][136];      // 17 KB (tf32-rounded V tile, padded)

    for (int k = t; k < NN / 4; k += 256)
        reinterpret_cast<float4*>(s2s)[k] = reinterpret_cast<const float4*>(g_s2)[k];

    const float s1a = g_s1[i0 + r1];
    const float s1b = g_s1[i0 + r2];

    float cacc[4][4];
#pragma unroll
    for (int nf = 0; nf < 4; nf++)
#pragma unroll
        for (int q = 0; q < 4; q++) cacc[nf][q] = 0.f;
    float zr1 = 0.f, zr2 = 0.f;
    __syncthreads();

    for (int j0 = jlo; j0 < jlo + KSJ; j0 += 32) {
        // load + tf32-round V tile (32 x 128)
#pragma unroll
        for (int q = 0; q < 4; q++) {
            const int e = t + q * 256;
            const int rr = e >> 5, cc = (e & 31) << 2;
            float4 v = *reinterpret_cast<const float4*>(g_W1h + (size_t)(j0 + rr) * HH + cc);
            v.x = tfr(v.x); v.y = tfr(v.y); v.z = tfr(v.z); v.w = tfr(v.w);
            *reinterpret_cast<float4*>(&Vt[rr][cc]) = v;
        }
        __syncthreads();

        const unsigned wd1 = g_M3[(size_t)(i0 + r1) * NW + (j0 >> 5)];
        const unsigned wd2 = g_M3[(size_t)(i0 + r2) * NW + (j0 >> 5)];
#pragma unroll
        for (int ks = 0; ks < 4; ks++) {
            const int cA = ks * 8 + tig, cB = cA + 4;
            const float s2A = s2s[j0 + cA], s2B = s2s[j0 + cB];
            const float eA1 = s1a + s2A, eA2 = s1b + s2A;
            const float eB1 = s1a + s2B, eB2 = s1b + s2B;
            float p0 = ((wd1 >> cA) & 1u) ? __expf(fmaxf(eA1, 0.2f * eA1) - 40.f) : 0.f;
            float p1 = ((wd2 >> cA) & 1u) ? __expf(fmaxf(eA2, 0.2f * eA2) - 40.f) : 0.f;
            float p2 = ((wd1 >> cB) & 1u) ? __expf(fmaxf(eB1, 0.2f * eB1) - 40.f) : 0.f;
            float p3 = ((wd2 >> cB) & 1u) ? __expf(fmaxf(eB2, 0.2f * eB2) - 40.f) : 0.f;
            p0 = tfr(p0); p1 = tfr(p1); p2 = tfr(p2); p3 = tfr(p3);
            if (wn == 0) { zr1 += p0 + p2; zr2 += p1 + p3; }
            unsigned a[4] = { __float_as_uint(p0), __float_as_uint(p1),
                              __float_as_uint(p2), __float_as_uint(p3) };
#pragma unroll
            for (int nf = 0; nf < 4; nf++) {
                const int ch = wn * 32 + nf * 8 + gid;
                unsigned b[2] = { __float_as_uint(Vt[cA][ch]),
                                  __float_as_uint(Vt[cB][ch]) };
                mma_tf32(cacc[nf], a, b);
            }
        }
        __syncthreads();
    }

    if (wn == 0) {
        zr1 += __shfl_xor_sync(0xFFFFFFFFu, zr1, 1);
        zr1 += __shfl_xor_sync(0xFFFFFFFFu, zr1, 2);
        zr2 += __shfl_xor_sync(0xFFFFFFFFu, zr2, 1);
        zr2 += __shfl_xor_sync(0xFFFFFFFFu, zr2, 2);
        if (tig == 0) {
            g_zp[blockIdx.y * NN + i0 + r1] = zr1;
            g_zp[blockIdx.y * NN + i0 + r2] = zr2;
        }
    }
    float* P = g_hp + (size_t)blockIdx.y * NN * HH;
#pragma unroll
    for (int nf = 0; nf < 4; nf++) {
        const int ch = wn * 32 + nf * 8 + 2 * tig;
        P[(size_t)(i0 + r1) * HH + ch]     = cacc[nf][0];
        P[(size_t)(i0 + r1) * HH + ch + 1] = cacc[nf][1];
        P[(size_t)(i0 + r2) * HH + ch]     = cacc[nf][2];
        P[(size_t)(i0 + r2) * HH + ch + 1] = cacc[nf][3];
    }
}

// ---- combine split-K for attn1: g_hk = (p0+p1)/(z0+z1) ----------------------
__global__ void combine1_kernel() {
    const int i = blockIdx.x, t = threadIdx.x;
    const size_t ix = (size_t)i * HH + t;
    const float z = g_zp[i] + g_zp[NN + i];
    g_hk[ix] = (g_hp[ix] + g_hp[(size_t)NN * HH + ix]) / z;
}

// ---- K6t: scores = h @ W2h^T (masked exp), partials = P @ h -----------------
__global__ __launch_bounds__(256, 2) void dattn2_tc() {
    const int t = threadIdx.x, warp = t >> 5, lane = t & 31;
    const int gid = lane >> 2, tig = lane & 3;
    const int wm = warp >> 2, wn = warp & 3;
    const int i0 = blockIdx.x * 32;
    const int jlo = blockIdx.y * KSJ;
    const int r1 = wm * 16 + gid, r2 = r1 + 8;

    __shared__ float hq[32][136];      // Q rows (tf32-rounded)
    __shared__ float Bt[32][136];      // time-shared: W2h tile, then h_k tile
    __shared__ float Pst[32][40];      // P staging
    __shared__ float Zp[4][32];

#pragma unroll
    for (int q = 0; q < 4; q++) {
        const int e = t + q * 256;
        const int rr = e >> 5, cc = (e & 31) << 2;
        float4 v = *reinterpret_cast<const float4*>(g_hk + (size_t)(i0 + rr) * HH + cc);
        v.x = tfr(v.x); v.y = tfr(v.y); v.z = tfr(v.z); v.w = tfr(v.w);
        *reinterpret_cast<float4*>(&hq[rr][cc]) = v;
    }

    float cacc[4][4];
#pragma unroll
    for (int nf = 0; nf < 4; nf++)
#pragma unroll
        for (int q = 0; q < 4; q++) cacc[nf][q] = 0.f;
    float zr1 = 0.f, zr2 = 0.f;
    __syncthreads();

    for (int j0 = jlo; j0 < jlo + KSJ; j0 += 32) {
        // ---- load W2h tile (B of scores GEMM)
#pragma unroll
        for (int q = 0; q < 4; q++) {
            const int e = t + q * 256;
            const int rr = e >> 5, cc = (e & 31) << 2;
            float4 v = *reinterpret_cast<const float4*>(g_W2h + (size_t)(j0 + rr) * HH + cc);
            v.x = tfr(v.x); v.y = tfr(v.y); v.z = tfr(v.z); v.w = tfr(v.w);
            *reinterpret_cast<float4*>(&Bt[rr][cc]) = v;
        }
        __syncthreads();

        // ---- scores: S[32x32] = hq @ Bt^T  (warp: m16 rows, n8 j-cols)
        float sc[4] = {0.f, 0.f, 0.f, 0.f};
        const int jr = wn * 8 + gid;
#pragma unroll
        for (int ks = 0; ks < 16; ks++) {
            unsigned a[4] = { __float_as_uint(hq[r1][ks * 8 + tig]),
                              __float_as_uint(hq[r2][ks * 8 + tig]),
                              __float_as_uint(hq[r1][ks * 8 + tig + 4]),
                              __float_as_uint(hq[r2][ks * 8 + tig + 4]) };
            unsigned b[2] = { __float_as_uint(Bt[jr][ks * 8 + tig]),
                              __float_as_uint(Bt[jr][ks * 8 + tig + 4]) };
            mma_tf32(sc, a, b);
        }
        // ---- mask + exp + stage P
        const unsigned wd1 = g_M3[(size_t)(i0 + r1) * NW + (j0 >> 5)];
        const unsigned wd2 = g_M3[(size_t)(i0 + r2) * NW + (j0 >> 5)];
        const int jl = wn * 8 + 2 * tig;
        float p0 = ((wd1 >> jl) & 1u)       ? __expf(sc[0]) : 0.f;
        float p1 = ((wd1 >> (jl + 1)) & 1u) ? __expf(sc[1]) : 0.f;
        float p2 = ((wd2 >> jl) & 1u)       ? __expf(sc[2]) : 0.f;
        float p3 = ((wd2 >> (jl + 1)) & 1u) ? __expf(sc[3]) : 0.f;
        p0 = tfr(p0); p1 = tfr(p1); p2 = tfr(p2); p3 = tfr(p3);
        zr1 += p0 + p1; zr2 += p2 + p3;
        Pst[r1][jl]     = p0;
        Pst[r1][jl + 1] = p1;
        Pst[r2][jl]     = p2;
        Pst[r2][jl + 1] = p3;
        __syncthreads();

        // ---- load h_k tile (B of PV GEMM) into the same buffer
#pragma unroll
        for (int q = 0; q < 4; q++) {
            const int e = t + q * 256;
            const int rr = e >> 5, cc = (e & 31) << 2;
            float4 v = *reinterpret_cast<const float4*>(g_hk + (size_t)(j0 + rr) * HH + cc);
            v.x = tfr(v.x); v.y = tfr(v.y); v.z = tfr(v.z); v.w = tfr(v.w);
            *reinterpret_cast<float4*>(&Bt[rr][cc]) = v;
        }
        __syncthreads();

        // ---- PV: cacc += P(32xk32) @ h_k(k32 x 128)
#pragma unroll
        for (int ks = 0; ks < 4; ks++) {
            unsigned a[4] = { __float_as_uint(Pst[r1][ks * 8 + tig]),
                              __float_as_uint(Pst[r2][ks * 8 + tig]),
                              __float_as_uint(Pst[r1][ks * 8 + tig + 4]),
                              __float_as_uint(Pst[r2][ks * 8 + tig + 4]) };
#pragma unroll
            for (int nf = 0; nf < 4; nf++) {
                const int ch = wn * 32 + nf * 8 + gid;
                unsigned b[2] = { __float_as_uint(Bt[ks * 8 + tig][ch]),
                                  __float_as_uint(Bt[ks * 8 + tig + 4][ch]) };
                mma_tf32(cacc[nf], a, b);
            }
        }
        __syncthreads();
    }

    // ---- Z: reduce over tig lanes, then across the 4 wn warps (deterministic)
    zr1 += __shfl_xor_sync(0xFFFFFFFFu, zr1, 1);
    zr1 += __shfl_xor_sync(0xFFFFFFFFu, zr1, 2);
    zr2 += __shfl_xor_sync(0xFFFFFFFFu, zr2, 1);
    zr2 += __shfl_xor_sync(0xFFFFFFFFu, zr2, 2);
    if (tig == 0) { Zp[wn][r1] = zr1; Zp[wn][r2] = zr2; }
    __syncthreads();
    if (wn == 0 && tig == 0) {
        g_zp[blockIdx.y * NN + i0 + r1] = (Zp[0][r1] + Zp[1][r1]) + (Zp[2][r1] + Zp[3][r1]);
        g_zp[blockIdx.y * NN + i0 + r2] = (Zp[0][r2] + Zp[1][r2]) + (Zp[2][r2] + Zp[3][r2]);
    }
    float* P = g_hp + (size_t)blockIdx.y * NN * HH;
#pragma unroll
    for (int nf = 0; nf < 4; nf++) {
        const int ch = wn * 32 + nf * 8 + 2 * tig;
        P[(size_t)(i0 + r1) * HH + ch]     = cacc[nf][0];
        P[(size_t)(i0 + r1) * HH + ch + 1] = cacc[nf][1];
        P[(size_t)(i0 + r2) * HH + ch]     = cacc[nf][2];
        P[(size_t)(i0 + r2) * HH + ch + 1] = cacc[nf][3];
    }
}

// ---- combine split-K for attn2: Oacc += (p0+p1)/(z0+z1) ---------------------
__global__ void combine2_kernel(float* __restrict__ Oacc) {
    const int i = blockIdx.x, t = threadIdx.x;
    const size_t ix = (size_t)i * HH + t;
    const float z = g_zp[i] + g_zp[NN + i];
    Oacc[ix] += (g_hp[ix] + g_hp[(size_t)NN * HH + ix]) / z;
}

// ---------------- K7: U_out = U_l + O_l --------------------------------------
__global__ void final_kernel(const float* __restrict__ U, float* __restrict__ out) {
    const int g = blockIdx.x * 256 + threadIdx.x;
    out[g] = U[g] + out[NN * HH + g];
}

// ---------------- launch -----------------------------------------------------
extern "C" void kernel_launch(void* const* d_in, const int* in_sizes, int n_in,
                              void* d_out, int out_size) {
    const float* X  = (const float*)d_in[0];
    const float* A  = (const float*)d_in[1];
    const float* U  = (const float*)d_in[2];
    const float* W1 = (const float*)d_in[3];
    const float* W2 = (const float*)d_in[4];
    const float* r  = (const float*)d_in[5];
    float* out  = (float*)d_out;
    float* Oacc = out + (size_t)NN * HH;   // second half of output = O_l

    prep_kernel<<<NN / 32, 256>>>(X, W1, W2);
    s12_kernel<<<NN, 128>>>(r);
    maskbuild_kernel<<<NN * NN / 256, 256>>>(A);
    boolmm_kernel<<<NN, 128>>>(0);         // M2 = pattern(A^2)
    boolmm_kernel<<<NN, 128>>>(1);         // M3 = pattern(A^3)

    // hop 0 (sparse, ~17 nnz/row)
    sattn1_kernel<<<NN, 128>>>(0);
    sattn2_kernel<<<NN, 128>>>(0, Oacc, 0);   // overwrite (d_out is poisoned)
    // hop 1 (sparse, ~280 nnz/row)
    sattn1_kernel<<<NN, 128>>>(1);
    sattn2_kernel<<<NN, 128>>>(1, Oacc, 1);
    // hop 2 (dense, tensor cores, split-K = 2)
    dattn1_tc<<<dim3(NN / 32, 2), 256>>>();
    combine1_kernel<<<NN, 128>>>();
    dattn2_tc<<<dim3(NN / 32, 2), 256>>>();
    combine2_kernel<<<NN, 128>>>(Oacc);

    final_kernel<<<NN * HH / 256, 256>>>(U, out);
}

// round 5
// speedup vs baseline: 4.0405x; 1.0927x over previous
#include <cuda_runtime.h>

#define NN   4096
#define INF  256
#define HH   128
#define NW   128      // mask words per row
#define KSJ  2048     // j-range per K-split (split = 2)
#define NDB  256      // dense blocks: 128 m-tiles x 2 splits

// ---------------- scratch (device globals) -----------------------------------
__device__ float    g_W1h[NN * HH];
__device__ float    g_W2h[NN * HH];
__device__ float    g_s1[NN];
__device__ float    g_s2[NN];
__device__ unsigned g_M1[NN * NW];
__device__ unsigned g_M2[NN * NW];
__device__ unsigned g_M3[NN * NW];
__device__ float    g_hk0[NN * HH];     // per-hop h_k
__device__ float    g_hk1[NN * HH];
__device__ float    g_hk2[NN * HH];
__device__ float    g_O0[NN * HH];      // per-hop outputs (sparse hops)
__device__ float    g_O1[NN * HH];
__device__ float    g_hp[2 * NN * HH];  // dense split-K partials
__device__ float    g_zp[2 * NN];

// ---------------- shared-memory union ----------------------------------------
struct SmemD1 { float s2s[NN]; float Vt[32][136]; };
struct SmemD2 { float hq[32][136]; float Bt[32][136]; float Pst[32][40]; float Zp[4][32]; };
struct SmemSp { unsigned short idxs[NN]; float plist[NN]; int wsum[4]; float comb[HH + 4]; };
union __align__(16) SmemU { SmemD1 d1; SmemD2 d2; SmemSp sp; };

// ---------------- tf32 helpers -----------------------------------------------
__device__ __forceinline__ float tfr(float f) {
    unsigned u;
    asm("cvt.rna.tf32.f32 %0, %1;" : "=r"(u) : "f"(f));
    return __uint_as_float(u);
}
__device__ __forceinline__ void mma_tf32(float* c, const unsigned* a, const unsigned* b) {
    asm("mma.sync.aligned.m16n8k8.row.col.f32.tf32.tf32.f32 "
        "{%0,%1,%2,%3},{%4,%5,%6,%7},{%8,%9},{%0,%1,%2,%3};"
        : "+f"(c[0]), "+f"(c[1]), "+f"(c[2]), "+f"(c[3])
        : "r"(a[0]), "r"(a[1]), "r"(a[2]), "r"(a[3]), "r"(b[0]), "r"(b[1]));
}

// ---------------- K1: W1h = X@W1^T, W2h = X@W2^T -----------------------------
__global__ void prep_kernel(const float* __restrict__ X,
                            const float* __restrict__ W1,
                            const float* __restrict__ W2) {
    __shared__ float xs[32][INF];
    const int t    = threadIdx.x;
    const int row0 = blockIdx.x * 32;

    const float4* Xv  = reinterpret_cast<const float4*>(X + (size_t)row0 * INF);
    float4*       xsv = reinterpret_cast<float4*>(&xs[0][0]);
    for (int k = t; k < 32 * INF / 4; k += 256) xsv[k] = Xv[k];
    __syncthreads();

    const float* W = (t < HH) ? (W1 + (size_t)t * INF)
                              : (W2 + (size_t)(t - HH) * INF);
    float acc[32];
#pragma unroll
    for (int rr = 0; rr < 32; rr++) acc[rr] = 0.f;

    for (int c = 0; c < INF; c += 4) {
        float4 w4 = *reinterpret_cast<const float4*>(W + c);
#pragma unroll
        for (int rr = 0; rr < 32; rr++) {
            float4 x4 = *reinterpret_cast<const float4*>(&xs[rr][c]);
            acc[rr] += x4.x * w4.x + x4.y * w4.y + x4.z * w4.z + x4.w * w4.w;
        }
    }
#pragma unroll
    for (int rr = 0; rr < 32; rr++) {
        const int row = row0 + rr;
        if (t < HH) g_W1h[(size_t)row * HH + t] = acc[rr];
        else        g_W2h[(size_t)row * HH + (t - HH)] = acc[rr];
    }
}

// ---------------- K2: s1, s2 -------------------------------------------------
__global__ void s12_kernel(const float* __restrict__ r) {
    const int i = blockIdx.x, t = threadIdx.x;
    const float w  = g_W1h[(size_t)i * HH + t];
    float v1 = w * r[t];
    float v2 = w * r[HH + t];
#pragma unroll
    for (int o = 16; o; o >>= 1) {
        v1 += __shfl_xor_sync(0xFFFFFFFFu, v1, o);
        v2 += __shfl_xor_sync(0xFFFFFFFFu, v2, o);
    }
    __shared__ float sh1[4], sh2[4];
    if ((t & 31) == 0) { sh1[t >> 5] = v1; sh2[t >> 5] = v2; }
    __syncthreads();
    if (t == 0) g_s1[i] = sh1[0] + sh1[1] + sh1[2] + sh1[3];
    if (t == 1) g_s2[i] = sh2[0] + sh2[1] + sh2[2] + sh2[3];
}

// ---------------- K3: bitmask of A -------------------------------------------
__global__ void maskbuild_kernel(const float* __restrict__ A) {
    const int gid = blockIdx.x * 256 + threadIdx.x;
    const float a = A[gid];
    const unsigned b = __ballot_sync(0xFFFFFFFFu, a != 0.0f);
    if ((threadIdx.x & 31) == 0) g_M1[gid >> 5] = b;
}

// ---------------- K4: boolean mat-power --------------------------------------
__global__ void boolmm_kernel(int mode) {
    const unsigned* Min  = (mode == 0) ? g_M1 : g_M2;
    unsigned*       Mout = (mode == 0) ? g_M2 : g_M3;
    const int i = blockIdx.x, t = threadIdx.x;
    __shared__ unsigned sh[NW];
    sh[t] = g_M1[(size_t)i * NW + t];
    __syncthreads();
    unsigned acc = 0;
    for (int w = 0; w < NW; w++) {
        unsigned bits = sh[w];
        while (bits) {
            const int b = __ffs(bits) - 1;
            bits &= bits - 1;
            acc |= Min[(size_t)(w * 32 + b) * NW + t];
        }
    }
    Mout[(size_t)i * NW + t] = acc;
}

// ================= SPARSE device paths (256 threads) =========================

// attn1: h[i] = sum_j p_j W1h[j] / Z over masked j. Fused compact + p.
__device__ void sparse_attn1(const unsigned* __restrict__ M, int i,
                             float* __restrict__ hkout, SmemSp& s) {
    const int t = threadIdx.x, l = t & 31, w = t >> 5;
    int c = 0, sc = 0; unsigned word = 0;
    if (t < 128) {
        word = M[(size_t)i * NW + t];
        c = __popc(word); sc = c;
#pragma unroll
        for (int o = 1; o < 32; o <<= 1) {
            int v = __shfl_up_sync(0xFFFFFFFFu, sc, o);
            if (l >= o) sc += v;
        }
        if (l == 31) s.wsum[w] = sc;
    }
    __syncthreads();
    const int n = s.wsum[0] + s.wsum[1] + s.wsum[2] + s.wsum[3];
    if (t < 128) {
        int base = 0;
#pragma unroll
        for (int q = 0; q < 4; q++) if (q < w) base += s.wsum[q];
        int off = base + sc - c;
        const float s1i = g_s1[i];
        unsigned b = word;
        while (b) {
            const int bit = __ffs(b) - 1;
            b &= b - 1;
            const int j = t * 32 + bit;
            const float e  = s1i + g_s2[j];
            const float lr = fmaxf(e, 0.2f * e);
            s.idxs[off]  = (unsigned short)j;
            s.plist[off] = __expf(lr - 40.0f);
            off++;
        }
    }
    __syncthreads();

    // PV: two thread-halves over j-range halves
    const int h = t >> 7, tl = t & 127;
    int nh = ((n >> 1) + 3) & ~3; if (nh > n) nh = n;
    const int k0 = h ? nh : 0, k1 = h ? n : nh;
    float a0 = 0.f, a1 = 0.f, a2 = 0.f, a3 = 0.f;
    float z0 = 0.f, z1 = 0.f, z2 = 0.f, z3 = 0.f;
    int k = k0;
    for (; k + 4 <= k1; k += 4) {
        const float p0 = s.plist[k], p1 = s.plist[k+1], p2 = s.plist[k+2], p3 = s.plist[k+3];
        const int j0 = s.idxs[k], j1 = s.idxs[k+1], j2 = s.idxs[k+2], j3 = s.idxs[k+3];
        a0 = fmaf(p0, g_W1h[(size_t)j0 * HH + tl], a0); z0 += p0;
        a1 = fmaf(p1, g_W1h[(size_t)j1 * HH + tl], a1); z1 += p1;
        a2 = fmaf(p2, g_W1h[(size_t)j2 * HH + tl], a2); z2 += p2;
        a3 = fmaf(p3, g_W1h[(size_t)j3 * HH + tl], a3); z3 += p3;
    }
    for (; k < k1; k++) {
        const float p = s.plist[k];
        a0 = fmaf(p, g_W1h[(size_t)s.idxs[k] * HH + tl], a0); z0 += p;
    }
    const float acc = (a0 + a1) + (a2 + a3);
    const float z   = (z0 + z1) + (z2 + z3);
    if (h == 1) { s.comb[tl] = acc; if (tl == 0) s.comb[HH] = z; }
    __syncthreads();
    if (h == 0)
        hkout[(size_t)i * HH + tl] = (acc + s.comb[tl]) / (z + s.comb[HH]);
}

// attn2: O[i] = softmax_j(h_i . W2h[j]) @ h rows (masked j). 8-warp score phase.
__device__ void sparse_attn2(const unsigned* __restrict__ M, int i,
                             const float* __restrict__ hkin,
                             float* __restrict__ Oout, SmemSp& s) {
    const int t = threadIdx.x, l = t & 31, w = t >> 5;
    const float hv0 = hkin[(size_t)i * HH + l];
    const float hv1 = hkin[(size_t)i * HH + l + 32];
    const float hv2 = hkin[(size_t)i * HH + l + 64];
    const float hv3 = hkin[(size_t)i * HH + l + 96];

    int c = 0, sc = 0; unsigned word = 0;
    if (t < 128) {
        word = M[(size_t)i * NW + t];
        c = __popc(word); sc = c;
#pragma unroll
        for (int o = 1; o < 32; o <<= 1) {
            int v = __shfl_up_sync(0xFFFFFFFFu, sc, o);
            if (l >= o) sc += v;
        }
        if (l == 31) s.wsum[w] = sc;
    }
    __syncthreads();
    const int n = s.wsum[0] + s.wsum[1] + s.wsum[2] + s.wsum[3];
    if (t < 128) {
        int base = 0;
#pragma unroll
        for (int q = 0; q < 4; q++) if (q < w) base += s.wsum[q];
        int off = base + sc - c;
        unsigned b = word;
        while (b) {
            const int bit = __ffs(b) - 1;
            b &= b - 1;
            s.idxs[off++] = (unsigned short)(t * 32 + bit);
        }
    }
    __syncthreads();

    // scores: warp-per-j across 8 warps, 2-way unrolled
    int k = w;
    for (; k + 8 < n; k += 16) {
        const int ja = s.idxs[k], jb = s.idxs[k + 8];
        const float* Wa = g_W2h + (size_t)ja * HH;
        const float* Wb = g_W2h + (size_t)jb * HH;
        float da = hv0 * Wa[l] + hv1 * Wa[l+32] + hv2 * Wa[l+64] + hv3 * Wa[l+96];
        float db = hv0 * Wb[l] + hv1 * Wb[l+32] + hv2 * Wb[l+64] + hv3 * Wb[l+96];
#pragma unroll
        for (int o = 16; o; o >>= 1) {
            da += __shfl_xor_sync(0xFFFFFFFFu, da, o);
            db += __shfl_xor_sync(0xFFFFFFFFu, db, o);
        }
        if (l == 0) { s.plist[k] = __expf(da); s.plist[k + 8] = __expf(db); }
    }
    for (; k < n; k += 8) {
        const int j = s.idxs[k];
        const float* W = g_W2h + (size_t)j * HH;
        float d = hv0 * W[l] + hv1 * W[l+32] + hv2 * W[l+64] + hv3 * W[l+96];
#pragma unroll
        for (int o = 16; o; o >>= 1) d += __shfl_xor_sync(0xFFFFFFFFu, d, o);
        if (l == 0) s.plist[k] = __expf(d);
    }
    __syncthreads();

    // PV over hkin rows: two thread-halves
    const int h = t >> 7, tl = t & 127;
    int nh = ((n >> 1) + 3) & ~3; if (nh > n) nh = n;
    const int k0 = h ? nh : 0, k1 = h ? n : nh;
    float a0 = 0.f, a1 = 0.f, a2 = 0.f, a3 = 0.f;
    float z0 = 0.f, z1 = 0.f, z2 = 0.f, z3 = 0.f;
    k = k0;
    for (; k + 4 <= k1; k += 4) {
        const float p0 = s.plist[k], p1 = s.plist[k+1], p2 = s.plist[k+2], p3 = s.plist[k+3];
        const int j0 = s.idxs[k], j1 = s.idxs[k+1], j2 = s.idxs[k+2], j3 = s.idxs[k+3];
        a0 = fmaf(p0, hkin[(size_t)j0 * HH + tl], a0); z0 += p0;
        a1 = fmaf(p1, hkin[(size_t)j1 * HH + tl], a1); z1 += p1;
        a2 = fmaf(p2, hkin[(size_t)j2 * HH + tl], a2); z2 += p2;
        a3 = fmaf(p3, hkin[(size_t)j3 * HH + tl], a3); z3 += p3;
    }
    for (; k < k1; k++) {
        const float p = s.plist[k];
        a0 = fmaf(p, hkin[(size_t)s.idxs[k] * HH + tl], a0); z0 += p;
    }
    const float acc = (a0 + a1) + (a2 + a3);
    const float z   = (z0 + z1) + (z2 + z3);
    if (h == 1) { s.comb[tl] = acc; if (tl == 0) s.comb[HH] = z; }
    __syncthreads();
    if (h == 0)
        Oout[(size_t)i * HH + tl] = (acc + s.comb[tl]) / (z + s.comb[HH]);
}

// ================= DENSE tf32 tensor-core device paths =======================
// 8 warps as (wm 0..1) x (wn 0..3). Tile M=32 rows. mma m16n8k8 tf32.

__device__ void dense_attn1(SmemD1& s, int m, int ks) {
    const int t = threadIdx.x, warp = t >> 5, lane = t & 31;
    const int gid = lane >> 2, tig = lane & 3;
    const int wm = warp >> 2, wn = warp & 3;
    const int i0 = m * 32;
    const int jlo = ks * KSJ;
    const int r1 = wm * 16 + gid, r2 = r1 + 8;

    for (int k = t; k < NN / 4; k += 256)
        reinterpret_cast<float4*>(s.s2s)[k] = reinterpret_cast<const float4*>(g_s2)[k];

    const float s1a = g_s1[i0 + r1];
    const float s1b = g_s1[i0 + r2];

    float cacc[4][4];
#pragma unroll
    for (int nf = 0; nf < 4; nf++)
#pragma unroll
        for (int q = 0; q < 4; q++) cacc[nf][q] = 0.f;
    float zr1 = 0.f, zr2 = 0.f;
    __syncthreads();

    for (int j0 = jlo; j0 < jlo + KSJ; j0 += 32) {
#pragma unroll
        for (int q = 0; q < 4; q++) {
            const int e = t + q * 256;
            const int rr = e >> 5, cc = (e & 31) << 2;
            float4 v = *reinterpret_cast<const float4*>(g_W1h + (size_t)(j0 + rr) * HH + cc);
            v.x = tfr(v.x); v.y = tfr(v.y); v.z = tfr(v.z); v.w = tfr(v.w);
            *reinterpret_cast<float4*>(&s.Vt[rr][cc]) = v;
        }
        __syncthreads();

        const unsigned wd1 = g_M3[(size_t)(i0 + r1) * NW + (j0 >> 5)];
        const unsigned wd2 = g_M3[(size_t)(i0 + r2) * NW + (j0 >> 5)];
#pragma unroll
        for (int kss = 0; kss < 4; kss++) {
            const int cA = kss * 8 + tig, cB = cA + 4;
            const float s2A = s.s2s[j0 + cA], s2B = s.s2s[j0 + cB];
            const float eA1 = s1a + s2A, eA2 = s1b + s2A;
            const float eB1 = s1a + s2B, eB2 = s1b + s2B;
            float p0 = ((wd1 >> cA) & 1u) ? __expf(fmaxf(eA1, 0.2f * eA1) - 40.f) : 0.f;
            float p1 = ((wd2 >> cA) & 1u) ? __expf(fmaxf(eA2, 0.2f * eA2) - 40.f) : 0.f;
            float p2 = ((wd1 >> cB) & 1u) ? __expf(fmaxf(eB1, 0.2f * eB1) - 40.f) : 0.f;
            float p3 = ((wd2 >> cB) & 1u) ? __expf(fmaxf(eB2, 0.2f * eB2) - 40.f) : 0.f;
            p0 = tfr(p0); p1 = tfr(p1); p2 = tfr(p2); p3 = tfr(p3);
            if (wn == 0) { zr1 += p0 + p2; zr2 += p1 + p3; }
            unsigned a[4] = { __float_as_uint(p0), __float_as_uint(p1),
                              __float_as_uint(p2), __float_as_uint(p3) };
#pragma unroll
            for (int nf = 0; nf < 4; nf++) {
                const int ch = wn * 32 + nf * 8 + gid;
                unsigned b[2] = { __float_as_uint(s.Vt[cA][ch]),
                                  __float_as_uint(s.Vt[cB][ch]) };
                mma_tf32(cacc[nf], a, b);
            }
        }
        __syncthreads();
    }

    if (wn == 0) {
        zr1 += __shfl_xor_sync(0xFFFFFFFFu, zr1, 1);
        zr1 += __shfl_xor_sync(0xFFFFFFFFu, zr1, 2);
        zr2 += __shfl_xor_sync(0xFFFFFFFFu, zr2, 1);
        zr2 += __shfl_xor_sync(0xFFFFFFFFu, zr2, 2);
        if (tig == 0) {
            g_zp[ks * NN + i0 + r1] = zr1;
            g_zp[ks * NN + i0 + r2] = zr2;
        }
    }
    float* P = g_hp + (size_t)ks * NN * HH;
#pragma unroll
    for (int nf = 0; nf < 4; nf++) {
        const int ch = wn * 32 + nf * 8 + 2 * tig;
        P[(size_t)(i0 + r1) * HH + ch]     = cacc[nf][0];
        P[(size_t)(i0 + r1) * HH + ch + 1] = cacc[nf][1];
        P[(size_t)(i0 + r2) * HH + ch]     = cacc[nf][2];
        P[(size_t)(i0 + r2) * HH + ch + 1] = cacc[nf][3];
    }
}

__device__ void dense_attn2(SmemD2& s, int m, int ks) {
    const int t = threadIdx.x, warp = t >> 5, lane = t & 31;
    const int gid = lane >> 2, tig = lane & 3;
    const int wm = warp >> 2, wn = warp & 3;
    const int i0 = m * 32;
    const int jlo = ks * KSJ;
    const int r1 = wm * 16 + gid, r2 = r1 + 8;

#pragma unroll
    for (int q = 0; q < 4; q++) {
        const int e = t + q * 256;
        const int rr = e >> 5, cc = (e & 31) << 2;
        float4 v = *reinterpret_cast<const float4*>(g_hk2 + (size_t)(i0 + rr) * HH + cc);
        v.x = tfr(v.x); v.y = tfr(v.y); v.z = tfr(v.z); v.w = tfr(v.w);
        *reinterpret_cast<float4*>(&s.hq[rr][cc]) = v;
    }

    float cacc[4][4];
#pragma unroll
    for (int nf = 0; nf < 4; nf++)
#pragma unroll
        for (int q = 0; q < 4; q++) cacc[nf][q] = 0.f;
    float zr1 = 0.f, zr2 = 0.f;
    __syncthreads();

    for (int j0 = jlo; j0 < jlo + KSJ; j0 += 32) {
#pragma unroll
        for (int q = 0; q < 4; q++) {
            const int e = t + q * 256;
            const int rr = e >> 5, cc = (e & 31) << 2;
            float4 v = *reinterpret_cast<const float4*>(g_W2h + (size_t)(j0 + rr) * HH + cc);
            v.x = tfr(v.x); v.y = tfr(v.y); v.z = tfr(v.z); v.w = tfr(v.w);
            *reinterpret_cast<float4*>(&s.Bt[rr][cc]) = v;
        }
        __syncthreads();

        float sc[4] = {0.f, 0.f, 0.f, 0.f};
        const int jr = wn * 8 + gid;
#pragma unroll
        for (int kss = 0; kss < 16; kss++) {
            unsigned a[4] = { __float_as_uint(s.hq[r1][kss * 8 + tig]),
                              __float_as_uint(s.hq[r2][kss * 8 + tig]),
                              __float_as_uint(s.hq[r1][kss * 8 + tig + 4]),
                              __float_as_uint(s.hq[r2][kss * 8 + tig + 4]) };
            unsigned b[2] = { __float_as_uint(s.Bt[jr][kss * 8 + tig]),
                              __float_as_uint(s.Bt[jr][kss * 8 + tig + 4]) };
            mma_tf32(sc, a, b);
        }
        const unsigned wd1 = g_M3[(size_t)(i0 + r1) * NW + (j0 >> 5)];
        const unsigned wd2 = g_M3[(size_t)(i0 + r2) * NW + (j0 >> 5)];
        const int jl = wn * 8 + 2 * tig;
        float p0 = ((wd1 >> jl) & 1u)       ? __expf(sc[0]) : 0.f;
        float p1 = ((wd1 >> (jl + 1)) & 1u) ? __expf(sc[1]) : 0.f;
        float p2 = ((wd2 >> jl) & 1u)       ? __expf(sc[2]) : 0.f;
        float p3 = ((wd2 >> (jl + 1)) & 1u) ? __expf(sc[3]) : 0.f;
        p0 = tfr(p0); p1 = tfr(p1); p2 = tfr(p2); p3 = tfr(p3);
        zr1 += p0 + p1; zr2 += p2 + p3;
        s.Pst[r1][jl]     = p0;
        s.Pst[r1][jl + 1] = p1;
        s.Pst[r2][jl]     = p2;
        s.Pst[r2][jl + 1] = p3;
        __syncthreads();

#pragma unroll
        for (int q = 0; q < 4; q++) {
            const int e = t + q * 256;
            const int rr = e >> 5, cc = (e & 31) << 2;
            float4 v = *reinterpret_cast<const float4*>(g_hk2 + (size_t)(j0 + rr) * HH + cc);
            v.x = tfr(v.x); v.y = tfr(v.y); v.z = tfr(v.z); v.w = tfr(v.w);
            *reinterpret_cast<float4*>(&s.Bt[rr][cc]) = v;
        }
        __syncthreads();

#pragma unroll
        for (int kss = 0; kss < 4; kss++) {
            unsigned a[4] = { __float_as_uint(s.Pst[r1][kss * 8 + tig]),
                              __float_as_uint(s.Pst[r2][kss * 8 + tig]),
                              __float_as_uint(s.Pst[r1][kss * 8 + tig + 4]),
                              __float_as_uint(s.Pst[r2][kss * 8 + tig + 4]) };
#pragma unroll
            for (int nf = 0; nf < 4; nf++) {
                const int ch = wn * 32 + nf * 8 + gid;
                unsigned b[2] = { __float_as_uint(s.Bt[kss * 8 + tig][ch]),
                                  __float_as_uint(s.Bt[kss * 8 + tig + 4][ch]) };
                mma_tf32(cacc[nf], a, b);
            }
        }
        __syncthreads();
    }

    zr1 += __shfl_xor_sync(0xFFFFFFFFu, zr1, 1);
    zr1 += __shfl_xor_sync(0xFFFFFFFFu, zr1, 2);
    zr2 += __shfl_xor_sync(0xFFFFFFFFu, zr2, 1);
    zr2 += __shfl_xor_sync(0xFFFFFFFFu, zr2, 2);
    if (tig == 0) { s.Zp[wn][r1] = zr1; s.Zp[wn][r2] = zr2; }
    __syncthreads();
    if (wn == 0 && tig == 0) {
        g_zp[ks * NN + i0 + r1] = (s.Zp[0][r1] + s.Zp[1][r1]) + (s.Zp[2][r1] + s.Zp[3][r1]);
        g_zp[ks * NN + i0 + r2] = (s.Zp[0][r2] + s.Zp[1][r2]) + (s.Zp[2][r2] + s.Zp[3][r2]);
    }
    float* P = g_hp + (size_t)ks * NN * HH;
#pragma unroll
    for (int nf = 0; nf < 4; nf++) {
        const int ch = wn * 32 + nf * 8 + 2 * tig;
        P[(size_t)(i0 + r1) * HH + ch]     = cacc[nf][0];
        P[(size_t)(i0 + r1) * HH + ch + 1] = cacc[nf][1];
        P[(size_t)(i0 + r2) * HH + ch]     = cacc[nf][2];
        P[(size_t)(i0 + r2) * HH + ch + 1] = cacc[nf][3];
    }
}

// ================= merged stage kernels ======================================
__global__ __launch_bounds__(256) void stage1_kernel() {
    __shared__ SmemU sm;
    const int b = blockIdx.x;
    if (b < NDB)               dense_attn1(sm.d1, b >> 1, b & 1);
    else if (b < NDB + NN)     sparse_attn1(g_M1, b - NDB, g_hk0, sm.sp);
    else                       sparse_attn1(g_M2, b - (NDB + NN), g_hk1, sm.sp);
}

__global__ void combine1_kernel() {      // dense hop only
    const int i = blockIdx.x, t = threadIdx.x;
    const size_t ix = (size_t)i * HH + t;
    const float z = g_zp[i] + g_zp[NN + i];
    g_hk2[ix] = (g_hp[ix] + g_hp[(size_t)NN * HH + ix]) / z;
}

__global__ __launch_bounds__(256) void stage2_kernel() {
    __shared__ SmemU sm;
    const int b = blockIdx.x;
    if (b < NDB)               dense_attn2(sm.d2, b >> 1, b & 1);
    else if (b < NDB + NN)     sparse_attn2(g_M1, b - NDB, g_hk0, g_O0, sm.sp);
    else                       sparse_attn2(g_M2, b - (NDB + NN), g_hk1, g_O1, sm.sp);
}

// ---------------- final: O = O0 + O1 + dense; out = (U + O, O) ---------------
__global__ void final_kernel(const float* __restrict__ U, float* __restrict__ out) {
    const int i = blockIdx.x, t = threadIdx.x;
    const size_t ix = (size_t)i * HH + t;
    const float z = g_zp[i] + g_zp[NN + i];
    const float Od = (g_hp[ix] + g_hp[(size_t)NN * HH + ix]) / z;
    const float O  = g_O0[ix] + g_O1[ix] + Od;
    out[ix] = U[ix] + O;
    out[(size_t)NN * HH + ix] = O;
}

// ---------------- launch -----------------------------------------------------
extern "C" void kernel_launch(void* const* d_in, const int* in_sizes, int n_in,
                              void* d_out, int out_size) {
    const float* X  = (const float*)d_in[0];
    const float* A  = (const float*)d_in[1];
    const float* U  = (const float*)d_in[2];
    const float* W1 = (const float*)d_in[3];
    const float* W2 = (const float*)d_in[4];
    const float* r  = (const float*)d_in[5];
    float* out = (float*)d_out;

    prep_kernel<<<NN / 32, 256>>>(X, W1, W2);
    s12_kernel<<<NN, 128>>>(r);
    maskbuild_kernel<<<NN * NN / 256, 256>>>(A);
    boolmm_kernel<<<NN, 128>>>(0);       // M2 = pattern(A^2)
    boolmm_kernel<<<NN, 128>>>(1);       // M3 = pattern(A^3)

    stage1_kernel<<<NDB + 2 * NN, 256>>>();   // all three hops' attn-1
    combine1_kernel<<<NN, 128>>>();           // dense split-K merge
    stage2_kernel<<<NDB + 2 * NN, 256>>>();   // all three hops' attn-2
    final_kernel<<<NN, 128>>>(U, out);
}

// round 6
// speedup vs baseline: 4.2721x; 1.0573x over previous
#include <cuda_runtime.h>

#define NN   4096
#define INF  256
#define HH   128
#define NW   128      // mask words per row
#define KSJ  2048     // j-range per K-split (split = 2)
#define NMB  (NN * NN / 256)   // maskbuild blocks

// ---------------- scratch (device globals) -----------------------------------
__device__ float    g_W1h[NN * HH];
__device__ float    g_W2h[NN * HH];
__device__ float    g_s1[NN];
__device__ float    g_s2[NN];
__device__ unsigned g_M1[NN * NW];
__device__ unsigned g_M2[NN * NW];
__device__ unsigned g_M3[NN * NW];
__device__ float    g_hk0[NN * HH];     // per-hop h_k (sparse hops)
__device__ float    g_hk1[NN * HH];
__device__ float    g_hk2[NN * HH];     // dense hop h_k (combined)
__device__ float    g_O0[NN * HH];      // per-hop outputs (sparse hops)
__device__ float    g_O1[NN * HH];
__device__ float    g_hp[2 * NN * HH];  // dense split-K partials
__device__ float    g_zp[2 * NN];

// ---------------- tf32 helpers -----------------------------------------------
__device__ __forceinline__ float tfr(float f) {
    unsigned u;
    asm("cvt.rna.tf32.f32 %0, %1;" : "=r"(u) : "f"(f));
    return __uint_as_float(u);
}
__device__ __forceinline__ void mma_tf32(float* c, const unsigned* a, const unsigned* b) {
    asm("mma.sync.aligned.m16n8k8.row.col.f32.tf32.tf32.f32 "
        "{%0,%1,%2,%3},{%4,%5,%6,%7},{%8,%9},{%0,%1,%2,%3};"
        : "+f"(c[0]), "+f"(c[1]), "+f"(c[2]), "+f"(c[3])
        : "r"(a[0]), "r"(a[1]), "r"(a[2]), "r"(a[3]), "r"(b[0]), "r"(b[1]));
}

// ---------------- K1: W1h = X@W1^T, W2h = X@W2^T -----------------------------
__global__ void prep_kernel(const float* __restrict__ X,
                            const float* __restrict__ W1,
                            const float* __restrict__ W2) {
    __shared__ float xs[32][INF];
    const int t    = threadIdx.x;
    const int row0 = blockIdx.x * 32;

    const float4* Xv  = reinterpret_cast<const float4*>(X + (size_t)row0 * INF);
    float4*       xsv = reinterpret_cast<float4*>(&xs[0][0]);
    for (int k = t; k < 32 * INF / 4; k += 256) xsv[k] = Xv[k];
    __syncthreads();

    const float* W = (t < HH) ? (W1 + (size_t)t * INF)
                              : (W2 + (size_t)(t - HH) * INF);
    float acc[32];
#pragma unroll
    for (int rr = 0; rr < 32; rr++) acc[rr] = 0.f;

    for (int c = 0; c < INF; c += 4) {
        float4 w4 = *reinterpret_cast<const float4*>(W + c);
#pragma unroll
        for (int rr = 0; rr < 32; rr++) {
            float4 x4 = *reinterpret_cast<const float4*>(&xs[rr][c]);
            acc[rr] += x4.x * w4.x + x4.y * w4.y + x4.z * w4.z + x4.w * w4.w;
        }
    }
#pragma unroll
    for (int rr = 0; rr < 32; rr++) {
        const int row = row0 + rr;
        if (t < HH) g_W1h[(size_t)row * HH + t] = acc[rr];
        else        g_W2h[(size_t)row * HH + (t - HH)] = acc[rr];
    }
}

// ---------------- K2: maskbuild + s12 (heterogeneous grid) -------------------
__global__ void mask_s12_kernel(const float* __restrict__ A,
                                const float* __restrict__ r) {
    const int b = blockIdx.x, t = threadIdx.x;
    if (b < NMB) {
        const int gid = b * 256 + t;
        const float a = A[gid];
        const unsigned w = __ballot_sync(0xFFFFFFFFu, a != 0.0f);
        if ((t & 31) == 0) g_M1[gid >> 5] = w;
        return;
    }
    // s12 path: one block per row i
    const int i = b - NMB;
    __shared__ float sh1[4], sh2[4];
    if (t < 128) {
        const float w  = g_W1h[(size_t)i * HH + t];
        float v1 = w * r[t];
        float v2 = w * r[HH + t];
#pragma unroll
        for (int o = 16; o; o >>= 1) {
            v1 += __shfl_xor_sync(0xFFFFFFFFu, v1, o);
            v2 += __shfl_xor_sync(0xFFFFFFFFu, v2, o);
        }
        if ((t & 31) == 0) { sh1[t >> 5] = v1; sh2[t >> 5] = v2; }
    }
    __syncthreads();
    if (t == 0) g_s1[i] = sh1[0] + sh1[1] + sh1[2] + sh1[3];
    if (t == 1) g_s2[i] = sh2[0] + sh2[1] + sh2[2] + sh2[3];
}

// ---------------- K3: boolean mat-power --------------------------------------
__global__ void boolmm_kernel(int mode) {
    const unsigned* Min  = (mode == 0) ? g_M1 : g_M2;
    unsigned*       Mout = (mode == 0) ? g_M2 : g_M3;
    const int i = blockIdx.x, t = threadIdx.x;
    __shared__ unsigned sh[NW];
    sh[t] = g_M1[(size_t)i * NW + t];
    __syncthreads();
    unsigned acc = 0;
    for (int w = 0; w < NW; w++) {
        unsigned bits = sh[w];
        while (bits) {
            const int b = __ffs(bits) - 1;
            bits &= bits - 1;
            acc |= Min[(size_t)(w * 32 + b) * NW + t];
        }
    }
    Mout[(size_t)i * NW + t] = acc;
}

// ================= SPARSE kernels (256 threads, lean) ========================

// attn1: h[i] = sum_j p_j W1h[j] / Z over masked j.
__global__ __launch_bounds__(256) void sattn1_kernel(int hop) {
    const unsigned* M = (hop == 0) ? g_M1 : g_M2;
    float* hkout      = (hop == 0) ? g_hk0 : g_hk1;
    const int i = blockIdx.x;
    __shared__ unsigned short idxs[NN];
    __shared__ float plist[NN];
    __shared__ int   wsum[4];
    __shared__ float comb[HH + 4];

    const int t = threadIdx.x, l = t & 31, w = t >> 5;
    int c = 0, sc = 0; unsigned word = 0;
    if (t < 128) {
        word = M[(size_t)i * NW + t];
        c = __popc(word); sc = c;
#pragma unroll
        for (int o = 1; o < 32; o <<= 1) {
            int v = __shfl_up_sync(0xFFFFFFFFu, sc, o);
            if (l >= o) sc += v;
        }
        if (l == 31) wsum[w] = sc;
    }
    __syncthreads();
    const int n = wsum[0] + wsum[1] + wsum[2] + wsum[3];
    if (t < 128) {
        int base = 0;
#pragma unroll
        for (int q = 0; q < 4; q++) if (q < w) base += wsum[q];
        int off = base + sc - c;
        const float s1i = g_s1[i];
        unsigned b = word;
        while (b) {
            const int bit = __ffs(b) - 1;
            b &= b - 1;
            const int j = t * 32 + bit;
            const float e  = s1i + g_s2[j];
            const float lr = fmaxf(e, 0.2f * e);
            idxs[off]  = (unsigned short)j;
            plist[off] = __expf(lr - 40.0f);
            off++;
        }
    }
    __syncthreads();

    // PV: two thread-halves over j-range halves
    const int h = t >> 7, tl = t & 127;
    int nh = ((n >> 1) + 3) & ~3; if (nh > n) nh = n;
    const int k0 = h ? nh : 0, k1 = h ? n : nh;
    float a0 = 0.f, a1 = 0.f, a2 = 0.f, a3 = 0.f;
    float z0 = 0.f, z1 = 0.f, z2 = 0.f, z3 = 0.f;
    int k = k0;
    for (; k + 4 <= k1; k += 4) {
        const float p0 = plist[k], p1 = plist[k+1], p2 = plist[k+2], p3 = plist[k+3];
        const int j0 = idxs[k], j1 = idxs[k+1], j2 = idxs[k+2], j3 = idxs[k+3];
        a0 = fmaf(p0, g_W1h[(size_t)j0 * HH + tl], a0); z0 += p0;
        a1 = fmaf(p1, g_W1h[(size_t)j1 * HH + tl], a1); z1 += p1;
        a2 = fmaf(p2, g_W1h[(size_t)j2 * HH + tl], a2); z2 += p2;
        a3 = fmaf(p3, g_W1h[(size_t)j3 * HH + tl], a3); z3 += p3;
    }
    for (; k < k1; k++) {
        const float p = plist[k];
        a0 = fmaf(p, g_W1h[(size_t)idxs[k] * HH + tl], a0); z0 += p;
    }
    const float acc = (a0 + a1) + (a2 + a3);
    const float z   = (z0 + z1) + (z2 + z3);
    if (h == 1) { comb[tl] = acc; if (tl == 0) comb[HH] = z; }
    __syncthreads();
    if (h == 0)
        hkout[(size_t)i * HH + tl] = (acc + comb[tl]) / (z + comb[HH]);
}

// attn2: O[i] = softmax_j(h_i . W2h[j]) @ h rows (masked j).
__global__ __launch_bounds__(256) void sattn2_kernel(int hop) {
    const unsigned* M  = (hop == 0) ? g_M1 : g_M2;
    const float* hkin  = (hop == 0) ? g_hk0 : g_hk1;
    float* Oout        = (hop == 0) ? g_O0 : g_O1;
    const int i = blockIdx.x;
    __shared__ unsigned short idxs[NN];
    __shared__ float plist[NN];
    __shared__ int   wsum[4];
    __shared__ float comb[HH + 4];

    const int t = threadIdx.x, l = t & 31, w = t >> 5;
    const float hv0 = hkin[(size_t)i * HH + l];
    const float hv1 = hkin[(size_t)i * HH + l + 32];
    const float hv2 = hkin[(size_t)i * HH + l + 64];
    const float hv3 = hkin[(size_t)i * HH + l + 96];

    int c = 0, sc = 0; unsigned word = 0;
    if (t < 128) {
        word = M[(size_t)i * NW + t];
        c = __popc(word); sc = c;
#pragma unroll
        for (int o = 1; o < 32; o <<= 1) {
            int v = __shfl_up_sync(0xFFFFFFFFu, sc, o);
            if (l >= o) sc += v;
        }
        if (l == 31) wsum[w] = sc;
    }
    __syncthreads();
    const int n = wsum[0] + wsum[1] + wsum[2] + wsum[3];
    if (t < 128) {
        int base = 0;
#pragma unroll
        for (int q = 0; q < 4; q++) if (q < w) base += wsum[q];
        int off = base + sc - c;
        unsigned b = word;
        while (b) {
            const int bit = __ffs(b) - 1;
            b &= b - 1;
            idxs[off++] = (unsigned short)(t * 32 + bit);
        }
    }
    __syncthreads();

    // scores: warp-per-j across 8 warps, 2-way unrolled
    int k = w;
    for (; k + 8 < n; k += 16) {
        const int ja = idxs[k], jb = idxs[k + 8];
        const float* Wa = g_W2h + (size_t)ja * HH;
        const float* Wb = g_W2h + (size_t)jb * HH;
        float da = hv0 * Wa[l] + hv1 * Wa[l+32] + hv2 * Wa[l+64] + hv3 * Wa[l+96];
        float db = hv0 * Wb[l] + hv1 * Wb[l+32] + hv2 * Wb[l+64] + hv3 * Wb[l+96];
#pragma unroll
        for (int o = 16; o; o >>= 1) {
            da += __shfl_xor_sync(0xFFFFFFFFu, da, o);
            db += __shfl_xor_sync(0xFFFFFFFFu, db, o);
        }
        if (l == 0) { plist[k] = __expf(da); plist[k + 8] = __expf(db); }
    }
    for (; k < n; k += 8) {
        const int j = idxs[k];
        const float* W = g_W2h + (size_t)j * HH;
        float d = hv0 * W[l] + hv1 * W[l+32] + hv2 * W[l+64] + hv3 * W[l+96];
#pragma unroll
        for (int o = 16; o; o >>= 1) d += __shfl_xor_sync(0xFFFFFFFFu, d, o);
        if (l == 0) plist[k] = __expf(d);
    }
    __syncthreads();

    // PV over hkin rows: two thread-halves
    const int h = t >> 7, tl = t & 127;
    int nh = ((n >> 1) + 3) & ~3; if (nh > n) nh = n;
    const int k0 = h ? nh : 0, k1 = h ? n : nh;
    float a0 = 0.f, a1 = 0.f, a2 = 0.f, a3 = 0.f;
    float z0 = 0.f, z1 = 0.f, z2 = 0.f, z3 = 0.f;
    k = k0;
    for (; k + 4 <= k1; k += 4) {
        const float p0 = plist[k], p1 = plist[k+1], p2 = plist[k+2], p3 = plist[k+3];
        const int j0 = idxs[k], j1 = idxs[k+1], j2 = idxs[k+2], j3 = idxs[k+3];
        a0 = fmaf(p0, hkin[(size_t)j0 * HH + tl], a0); z0 += p0;
        a1 = fmaf(p1, hkin[(size_t)j1 * HH + tl], a1); z1 += p1;
        a2 = fmaf(p2, hkin[(size_t)j2 * HH + tl], a2); z2 += p2;
        a3 = fmaf(p3, hkin[(size_t)j3 * HH + tl], a3); z3 += p3;
    }
    for (; k < k1; k++) {
        const float p = plist[k];
        a0 = fmaf(p, hkin[(size_t)idxs[k] * HH + tl], a0); z0 += p;
    }
    const float acc = (a0 + a1) + (a2 + a3);
    const float z   = (z0 + z1) + (z2 + z3);
    if (h == 1) { comb[tl] = acc; if (tl == 0) comb[HH] = z; }
    __syncthreads();
    if (h == 0)
        Oout[(size_t)i * HH + tl] = (acc + comb[tl]) / (z + comb[HH]);
}

// ================= DENSE tf32 tensor-core kernels ============================
// 8 warps as (wm 0..1) x (wn 0..3). Tile M=32 rows. grid (128 mtiles, 2 splits).

__global__ __launch_bounds__(256, 2) void dattn1_tc() {
    __shared__ float s2s[NN];
    __shared__ float Vt[32][136];
    const int t = threadIdx.x, warp = t >> 5, lane = t & 31;
    const int gid = lane >> 2, tig = lane & 3;
    const int wm = warp >> 2, wn = warp & 3;
    const int i0 = blockIdx.x * 32;
    const int jlo = blockIdx.y * KSJ;
    const int r1 = wm * 16 + gid, r2 = r1 + 8;

    for (int k = t; k < NN / 4; k += 256)
        reinterpret_cast<float4*>(s2s)[k] = reinterpret_cast<const float4*>(g_s2)[k];

    const float s1a = g_s1[i0 + r1];
    const float s1b = g_s1[i0 + r2];

    float cacc[4][4];
#pragma unroll
    for (int nf = 0; nf < 4; nf++)
#pragma unroll
        for (int q = 0; q < 4; q++) cacc[nf][q] = 0.f;
    float zr1 = 0.f, zr2 = 0.f;
    __syncthreads();

    for (int j0 = jlo; j0 < jlo + KSJ; j0 += 32) {
#pragma unroll
        for (int q = 0; q < 4; q++) {
            const int e = t + q * 256;
            const int rr = e >> 5, cc = (e & 31) << 2;
            float4 v = *reinterpret_cast<const float4*>(g_W1h + (size_t)(j0 + rr) * HH + cc);
            v.x = tfr(v.x); v.y = tfr(v.y); v.z = tfr(v.z); v.w = tfr(v.w);
            *reinterpret_cast<float4*>(&Vt[rr][cc]) = v;
        }
        __syncthreads();

        const unsigned wd1 = g_M3[(size_t)(i0 + r1) * NW + (j0 >> 5)];
        const unsigned wd2 = g_M3[(size_t)(i0 + r2) * NW + (j0 >> 5)];
#pragma unroll
        for (int kss = 0; kss < 4; kss++) {
            const int cA = kss * 8 + tig, cB = cA + 4;
            const float s2A = s2s[j0 + cA], s2B = s2s[j0 + cB];
            const float eA1 = s1a + s2A, eA2 = s1b + s2A;
            const float eB1 = s1a + s2B, eB2 = s1b + s2B;
            float p0 = ((wd1 >> cA) & 1u) ? __expf(fmaxf(eA1, 0.2f * eA1) - 40.f) : 0.f;
            float p1 = ((wd2 >> cA) & 1u) ? __expf(fmaxf(eA2, 0.2f * eA2) - 40.f) : 0.f;
            float p2 = ((wd1 >> cB) & 1u) ? __expf(fmaxf(eB1, 0.2f * eB1) - 40.f) : 0.f;
            float p3 = ((wd2 >> cB) & 1u) ? __expf(fmaxf(eB2, 0.2f * eB2) - 40.f) : 0.f;
            p0 = tfr(p0); p1 = tfr(p1); p2 = tfr(p2); p3 = tfr(p3);
            if (wn == 0) { zr1 += p0 + p2; zr2 += p1 + p3; }
            unsigned a[4] = { __float_as_uint(p0), __float_as_uint(p1),
                              __float_as_uint(p2), __float_as_uint(p3) };
#pragma unroll
            for (int nf = 0; nf < 4; nf++) {
                const int ch = wn * 32 + nf * 8 + gid;
                unsigned b[2] = { __float_as_uint(Vt[cA][ch]),
                                  __float_as_uint(Vt[cB][ch]) };
                mma_tf32(cacc[nf], a, b);
            }
        }
        __syncthreads();
    }

    if (wn == 0) {
        zr1 += __shfl_xor_sync(0xFFFFFFFFu, zr1, 1);
        zr1 += __shfl_xor_sync(0xFFFFFFFFu, zr1, 2);
        zr2 += __shfl_xor_sync(0xFFFFFFFFu, zr2, 1);
        zr2 += __shfl_xor_sync(0xFFFFFFFFu, zr2, 2);
        if (tig == 0) {
            g_zp[blockIdx.y * NN + i0 + r1] = zr1;
            g_zp[blockIdx.y * NN + i0 + r2] = zr2;
        }
    }
    float* P = g_hp + (size_t)blockIdx.y * NN * HH;
#pragma unroll
    for (int nf = 0; nf < 4; nf++) {
        const int ch = wn * 32 + nf * 8 + 2 * tig;
        P[(size_t)(i0 + r1) * HH + ch]     = cacc[nf][0];
        P[(size_t)(i0 + r1) * HH + ch + 1] = cacc[nf][1];
        P[(size_t)(i0 + r2) * HH + ch]     = cacc[nf][2];
        P[(size_t)(i0 + r2) * HH + ch + 1] = cacc[nf][3];
    }
}

__global__ void combine1_kernel() {      // dense hop split-K merge
    const int i = blockIdx.x, t = threadIdx.x;
    const size_t ix = (size_t)i * HH + t;
    const float z = g_zp[i] + g_zp[NN + i];
    g_hk2[ix] = (g_hp[ix] + g_hp[(size_t)NN * HH + ix]) / z;
}

__global__ __launch_bounds__(256, 2) void dattn2_tc() {
    __shared__ float hq[32][136];
    __shared__ float Bt[32][136];
    __shared__ float Pst[32][40];
    __shared__ float Zp[4][32];
    const int t = threadIdx.x, warp = t >> 5, lane = t & 31;
    const int gid = lane >> 2, tig = lane & 3;
    const int wm = warp >> 2, wn = warp & 3;
    const int i0 = blockIdx.x * 32;
    const int jlo = blockIdx.y * KSJ;
    const int r1 = wm * 16 + gid, r2 = r1 + 8;

#pragma unroll
    for (int q = 0; q < 4; q++) {
        const int e = t + q * 256;
        const int rr = e >> 5, cc = (e & 31) << 2;
        float4 v = *reinterpret_cast<const float4*>(g_hk2 + (size_t)(i0 + rr) * HH + cc);
        v.x = tfr(v.x); v.y = tfr(v.y); v.z = tfr(v.z); v.w = tfr(v.w);
        *reinterpret_cast<float4*>(&hq[rr][cc]) = v;
    }

    float cacc[4][4];
#pragma unroll
    for (int nf = 0; nf < 4; nf++)
#pragma unroll
        for (int q = 0; q < 4; q++) cacc[nf][q] = 0.f;
    float zr1 = 0.f, zr2 = 0.f;
    __syncthreads();

    for (int j0 = jlo; j0 < jlo + KSJ; j0 += 32) {
#pragma unroll
        for (int q = 0; q < 4; q++) {
            const int e = t + q * 256;
            const int rr = e >> 5, cc = (e & 31) << 2;
            float4 v = *reinterpret_cast<const float4*>(g_W2h + (size_t)(j0 + rr) * HH + cc);
            v.x = tfr(v.x); v.y = tfr(v.y); v.z = tfr(v.z); v.w = tfr(v.w);
            *reinterpret_cast<float4*>(&Bt[rr][cc]) = v;
        }
        __syncthreads();

        float sc[4] = {0.f, 0.f, 0.f, 0.f};
        const int jr = wn * 8 + gid;
#pragma unroll
        for (int kss = 0; kss < 16; kss++) {
            unsigned a[4] = { __float_as_uint(hq[r1][kss * 8 + tig]),
                              __float_as_uint(hq[r2][kss * 8 + tig]),
                              __float_as_uint(hq[r1][kss * 8 + tig + 4]),
                              __float_as_uint(hq[r2][kss * 8 + tig + 4]) };
            unsigned b[2] = { __float_as_uint(Bt[jr][kss * 8 + tig]),
                              __float_as_uint(Bt[jr][kss * 8 + tig + 4]) };
            mma_tf32(sc, a, b);
        }
        const unsigned wd1 = g_M3[(size_t)(i0 + r1) * NW + (j0 >> 5)];
        const unsigned wd2 = g_M3[(size_t)(i0 + r2) * NW + (j0 >> 5)];
        const int jl = wn * 8 + 2 * tig;
        float p0 = ((wd1 >> jl) & 1u)       ? __expf(sc[0]) : 0.f;
        float p1 = ((wd1 >> (jl + 1)) & 1u) ? __expf(sc[1]) : 0.f;
        float p2 = ((wd2 >> jl) & 1u)       ? __expf(sc[2]) : 0.f;
        float p3 = ((wd2 >> (jl + 1)) & 1u) ? __expf(sc[3]) : 0.f;
        p0 = tfr(p0); p1 = tfr(p1); p2 = tfr(p2); p3 = tfr(p3);
        zr1 += p0 + p1; zr2 += p2 + p3;
        Pst[r1][jl]     = p0;
        Pst[r1][jl + 1] = p1;
        Pst[r2][jl]     = p2;
        Pst[r2][jl + 1] = p3;
        __syncthreads();

#pragma unroll
        for (int q = 0; q < 4; q++) {
            const int e = t + q * 256;
            const int rr = e >> 5, cc = (e & 31) << 2;
            float4 v = *reinterpret_cast<const float4*>(g_hk2 + (size_t)(j0 + rr) * HH + cc);
            v.x = tfr(v.x); v.y = tfr(v.y); v.z = tfr(v.z); v.w = tfr(v.w);
            *reinterpret_cast<float4*>(&Bt[rr][cc]) = v;
        }
        __syncthreads();

#pragma unroll
        for (int kss = 0; kss < 4; kss++) {
            unsigned a[4] = { __float_as_uint(Pst[r1][kss * 8 + tig]),
                              __float_as_uint(Pst[r2][kss * 8 + tig]),
                              __float_as_uint(Pst[r1][kss * 8 + tig + 4]),
                              __float_as_uint(Pst[r2][kss * 8 + tig + 4]) };
#pragma unroll
            for (int nf = 0; nf < 4; nf++) {
                const int ch = wn * 32 + nf * 8 + gid;
                unsigned b[2] = { __float_as_uint(Bt[kss * 8 + tig][ch]),
                                  __float_as_uint(Bt[kss * 8 + tig + 4][ch]) };
                mma_tf32(cacc[nf], a, b);
            }
        }
        __syncthreads();
    }

    zr1 += __shfl_xor_sync(0xFFFFFFFFu, zr1, 1);
    zr1 += __shfl_xor_sync(0xFFFFFFFFu, zr1, 2);
    zr2 += __shfl_xor_sync(0xFFFFFFFFu, zr2, 1);
    zr2 += __shfl_xor_sync(0xFFFFFFFFu, zr2, 2);
    if (tig == 0) { Zp[wn][r1] = zr1; Zp[wn][r2] = zr2; }
    __syncthreads();
    if (wn == 0 && tig == 0) {
        g_zp[blockIdx.y * NN + i0 + r1] = (Zp[0][r1] + Zp[1][r1]) + (Zp[2][r1] + Zp[3][r1]);
        g_zp[blockIdx.y * NN + i0 + r2] = (Zp[0][r2] + Zp[1][r2]) + (Zp[2][r2] + Zp[3][r2]);
    }
    float* P = g_hp + (size_t)blockIdx.y * NN * HH;
#pragma unroll
    for (int nf = 0; nf < 4; nf++) {
        const int ch = wn * 32 + nf * 8 + 2 * tig;
        P[(size_t)(i0 + r1) * HH + ch]     = cacc[nf][0];
        P[(size_t)(i0 + r1) * HH + ch + 1] = cacc[nf][1];
        P[(size_t)(i0 + r2) * HH + ch]     = cacc[nf][2];
        P[(size_t)(i0 + r2) * HH + ch + 1] = cacc[nf][3];
    }
}

// ---------------- final: O = O0 + O1 + dense; out = (U + O, O) ---------------
__global__ void final_kernel(const float* __restrict__ U, float* __restrict__ out) {
    const int i = blockIdx.x, t = threadIdx.x;
    const size_t ix = (size_t)i * HH + t;
    const float z = g_zp[i] + g_zp[NN + i];
    const float Od = (g_hp[ix] + g_hp[(size_t)NN * HH + ix]) / z;
    const float O  = g_O0[ix] + g_O1[ix] + Od;
    out[ix] = U[ix] + O;
    out[(size_t)NN * HH + ix] = O;
}

// ---------------- launch: fork sparse chain onto a side stream ---------------
extern "C" void kernel_launch(void* const* d_in, const int* in_sizes, int n_in,
                              void* d_out, int out_size) {
    const float* X  = (const float*)d_in[0];
    const float* A  = (const float*)d_in[1];
    const float* U  = (const float*)d_in[2];
    const float* W1 = (const float*)d_in[3];
    const float* W2 = (const float*)d_in[4];
    const float* r  = (const float*)d_in[5];
    float* out = (float*)d_out;

    cudaStream_t sB;
    cudaStreamCreateWithFlags(&sB, cudaStreamNonBlocking);
    cudaEvent_t eF, eM2, eJ;
    cudaEventCreateWithFlags(&eF,  cudaEventDisableTiming);
    cudaEventCreateWithFlags(&eM2, cudaEventDisableTiming);
    cudaEventCreateWithFlags(&eJ,  cudaEventDisableTiming);

    // main (default) stream: prep -> masks/s12 -> boolmm chain -> dense chain
    prep_kernel<<<NN / 32, 256>>>(X, W1, W2);
    mask_s12_kernel<<<NMB + NN, 256>>>(A, r);
    cudaEventRecord(eF, 0);                    // M1, s1/s2, W1h/W2h ready
    boolmm_kernel<<<NN, 128>>>(0);             // M2 = pattern(A^2)
    cudaEventRecord(eM2, 0);                   // M2 ready
    boolmm_kernel<<<NN, 128>>>(1);             // M3 = pattern(A^3)
    dattn1_tc<<<dim3(NN / 32, 2), 256>>>();
    combine1_kernel<<<NN, 128>>>();
    dattn2_tc<<<dim3(NN / 32, 2), 256>>>();

    // side stream: sparse hops, forked as early as dependencies allow
    cudaStreamWaitEvent(sB, eF, 0);
    sattn1_kernel<<<NN, 256, 0, sB>>>(0);      // hop 0 (needs M1)
    sattn2_kernel<<<NN, 256, 0, sB>>>(0);
    cudaStreamWaitEvent(sB, eM2, 0);
    sattn1_kernel<<<NN, 256, 0, sB>>>(1);      // hop 1 (needs M2)
    sattn2_kernel<<<NN, 256, 0, sB>>>(1);
    cudaEventRecord(eJ, sB);

    // join and finalize
    cudaStreamWaitEvent(0, eJ, 0);
    final_kernel<<<NN, 128>>>(U, out);
}